// round 4
// baseline (speedup 1.0000x reference)
#include <cuda_runtime.h>
#include <math.h>

#define B_   256
#define T_   512
#define IN_  128
#define H_   256
#define G3_  768          // 3*H
#define BT_  (B_ * T_)    // 131072
#define OUT_ 128
#define EPS_ 1e-5f

// ---------------- device-global scratch ----------------
__device__ float g_G [(size_t)BT_ * G3_];   // gi for current layer (reused)
__device__ float g_H1[(size_t)BT_ * H_];    // layer-1 hidden seq (b,t,h)
__device__ float g_H2[(size_t)BT_ * H_];    // layer-2 hidden seq (b,t,h)
__device__ float g_part[512 * 512];         // BN partial sums
__device__ float g_bnsum[2 * H_];
__device__ float g_sum[B_ * H_];
__device__ unsigned int g_ctr[2][32];       // per-layer, per-batch-group barrier counters

// ---------------- activations ----------------
__device__ __forceinline__ float fexp2a(float x) {
    float y;
    asm("ex2.approx.f32 %0, %1;" : "=f"(y) : "f"(x));
    return y;
}
__device__ __forceinline__ float fsigmoid(float x) {
    return 1.0f / (1.0f + fexp2a(-1.4426950408889634f * x));
}
__device__ __forceinline__ float ftanh(float x) {
    float e = fexp2a(2.8853900817779268f * x);
    return 1.0f - 2.0f / (e + 1.0f);
}
__device__ __forceinline__ unsigned int ldacq(const unsigned int* p) {
    unsigned int v;
    asm volatile("ld.acquire.gpu.u32 %0, [%1];" : "=r"(v) : "l"(p));
    return v;
}

// ---------------- counter reset ----------------
__global__ void k_reset() {
    ((unsigned int*)g_ctr)[threadIdx.x] = 0u;   // 64 threads
}

// ---------------- batched GEMM: g_G[BT,768] = A[BT,K] @ W[768,K]^T + bias ----------------
template <int SRC>
__global__ __launch_bounds__(256) void k_gemm(const float* __restrict__ Ain,
                                              const float* __restrict__ W,
                                              const float* __restrict__ bias,
                                              int K) {
    const float* A = (SRC == 0) ? Ain : g_H1;
    float* C = g_G;

    __shared__ float As[16][132];
    __shared__ float Ws[16][68];

    const int tid = threadIdx.x;
    const int m0 = blockIdx.x * 128;
    const int n0 = blockIdx.y * 64;
    const int tx = tid & 15;
    const int ty = tid >> 4;

    float acc[8][4];
#pragma unroll
    for (int i = 0; i < 8; i++)
#pragma unroll
        for (int j = 0; j < 4; j++) acc[i][j] = 0.0f;

    for (int k0 = 0; k0 < K; k0 += 16) {
#pragma unroll
        for (int i = 0; i < 2; i++) {
            int lin = tid + i * 256;
            int m = lin >> 2;
            int kk = (lin & 3) * 4;
            float4 v = *(const float4*)(A + (size_t)(m0 + m) * K + k0 + kk);
            As[kk + 0][m] = v.x; As[kk + 1][m] = v.y;
            As[kk + 2][m] = v.z; As[kk + 3][m] = v.w;
        }
        {
            int n = tid >> 2;
            int kk = (tid & 3) * 4;
            float4 v = *(const float4*)(W + (size_t)(n0 + n) * K + k0 + kk);
            Ws[kk + 0][n] = v.x; Ws[kk + 1][n] = v.y;
            Ws[kk + 2][n] = v.z; Ws[kk + 3][n] = v.w;
        }
        __syncthreads();
#pragma unroll
        for (int kk = 0; kk < 16; kk++) {
            float a[8], b[4];
#pragma unroll
            for (int i = 0; i < 8; i++) a[i] = As[kk][ty * 8 + i];
#pragma unroll
            for (int j = 0; j < 4; j++) b[j] = Ws[kk][tx * 4 + j];
#pragma unroll
            for (int i = 0; i < 8; i++)
#pragma unroll
                for (int j = 0; j < 4; j++) acc[i][j] = fmaf(a[i], b[j], acc[i][j]);
        }
        __syncthreads();
    }

#pragma unroll
    for (int i = 0; i < 8; i++) {
        int m = m0 + ty * 8 + i;
        int n = n0 + tx * 4;
        float4 v;
        v.x = acc[i][0] + bias[n + 0];
        v.y = acc[i][1] + bias[n + 1];
        v.z = acc[i][2] + bias[n + 2];
        v.w = acc[i][3] + bias[n + 3];
        *(float4*)(C + (size_t)m * G3_ + n) = v;
    }
}

// ---------------- persistent GRU recurrence (one kernel per layer) ----------------
// grid (32 batch-groups, 4 feature-groups), 256 threads, smem: weights + h_prev.
// thread: j = j0 + (tid>>2), b2 = (tid>>1)&1 (batch quad), ks = tid&1 (k half).
#define WPAD 260
#define SMEM_RECUR ((3 * 64 * WPAD + 8 * WPAD) * sizeof(float))

template <int LAYER>
__global__ __launch_bounds__(256) void k_recur(const float* __restrict__ whh,
                                               const float* __restrict__ bhh) {
    extern __shared__ float smem[];
    float* w_s = smem;                       // [3][64][WPAD]
    float* h_s = smem + 3 * 64 * WPAD;       // [8][WPAD]

    float* Hbuf = (LAYER == 1) ? g_H1 : g_H2;
    unsigned int* ctr = &g_ctr[LAYER - 1][blockIdx.x];

    const int tid = threadIdx.x;
    const int bg = blockIdx.x;               // batch group: batches bg*8..bg*8+7
    const int j0 = blockIdx.y * 64;

    // ---- preload weights into smem: w_s[g][jl][k], rows padded to WPAD ----
    for (int lin = tid; lin < 3 * 64 * 64; lin += 256) {   // float4 granules
        int g  = lin / (64 * 64);
        int r  = lin - g * 64 * 64;
        int jl = r >> 6;
        int q  = r & 63;
        float4 v = *(const float4*)(whh + (size_t)(g * 256 + j0 + jl) * H_ + 4 * q);
        *(float4*)(w_s + (g * 64 + jl) * WPAD + 4 * q) = v;
    }

    const int jl = tid >> 2;                 // 0..63
    const int b2 = (tid >> 1) & 1;           // 0..1 (batch quad)
    const int ks = tid & 1;                  // 0..1 (k half)
    const int j  = j0 + jl;                  // global feature
    const int bb = bg * 8 + b2 * 4;          // first batch of this thread's quad

    const float br = bhh[j], bz = bhh[j + 256], bn = bhh[j + 512];

    const float* wr  = w_s + (0 * 64 + jl) * WPAD;
    const float* wzp = w_s + (1 * 64 + jl) * WPAD;
    const float* wnp = w_s + (2 * 64 + jl) * WPAD;

    __syncthreads();

    for (int t = 0; t < T_; t++) {
        // ---- prefetch gi (DRAM) early; consumed ~6k cycles later ----
        float gir[4], giz[4], gin[4];
        if (ks == 0) {
#pragma unroll
            for (int c = 0; c < 4; c++) {
                size_t base = ((size_t)(bb + c) * T_ + t) * G3_ + j;
                gir[c] = g_G[base];
                giz[c] = g_G[base + 256];
                gin[c] = g_G[base + 512];
            }
        }

        // ---- stage h_prev into smem ----
        if (t == 0) {
#pragma unroll
            for (int lin = tid; lin < 512; lin += 256) {
                int b = lin >> 6, q = lin & 63;
                *(float4*)(h_s + b * WPAD + 4 * q) = make_float4(0.f, 0.f, 0.f, 0.f);
            }
        } else {
#pragma unroll
            for (int lin = tid; lin < 512; lin += 256) {
                int b = lin >> 6, q = lin & 63;
                float4 v = *(const float4*)(Hbuf +
                    ((size_t)(bg * 8 + b) * T_ + (t - 1)) * H_ + 4 * q);
                *(float4*)(h_s + b * WPAD + 4 * q) = v;
            }
        }
        __syncthreads();

        // ---- gate dot-products over this thread's k half ----
        float ar[4] = {0.f, 0.f, 0.f, 0.f};
        float az[4] = {0.f, 0.f, 0.f, 0.f};
        float an[4] = {0.f, 0.f, 0.f, 0.f};

#pragma unroll 4
        for (int i = 0; i < 32; i++) {
            int q = ((i + 4 * ks) & 31) + 32 * ks;   // ks=1 slice rotated (bank split)
            float4 w_r = *(const float4*)(wr  + 4 * q);
            float4 w_z = *(const float4*)(wzp + 4 * q);
            float4 w_n = *(const float4*)(wnp + 4 * q);
#pragma unroll
            for (int c = 0; c < 4; c++) {
                float4 hv = *(const float4*)(h_s + (b2 * 4 + c) * WPAD + 4 * q);
                ar[c] = fmaf(hv.x, w_r.x, ar[c]); ar[c] = fmaf(hv.y, w_r.y, ar[c]);
                ar[c] = fmaf(hv.z, w_r.z, ar[c]); ar[c] = fmaf(hv.w, w_r.w, ar[c]);
                az[c] = fmaf(hv.x, w_z.x, az[c]); az[c] = fmaf(hv.y, w_z.y, az[c]);
                az[c] = fmaf(hv.z, w_z.z, az[c]); az[c] = fmaf(hv.w, w_z.w, az[c]);
                an[c] = fmaf(hv.x, w_n.x, an[c]); an[c] = fmaf(hv.y, w_n.y, an[c]);
                an[c] = fmaf(hv.z, w_n.z, an[c]); an[c] = fmaf(hv.w, w_n.w, an[c]);
            }
        }

        // ---- combine k halves (lane bit 0 = ks) ----
#pragma unroll
        for (int c = 0; c < 4; c++) {
            ar[c] += __shfl_xor_sync(0xffffffffu, ar[c], 1);
            az[c] += __shfl_xor_sync(0xffffffffu, az[c], 1);
            an[c] += __shfl_xor_sync(0xffffffffu, an[c], 1);
        }

        // ---- epilogue: gates, new h, store ----
        if (ks == 0) {
#pragma unroll
            for (int c = 0; c < 4; c++) {
                float r = fsigmoid(gir[c] + ar[c] + br);
                float z = fsigmoid(giz[c] + az[c] + bz);
                float n = ftanh   (gin[c] + r * (an[c] + bn));
                float hp = h_s[(b2 * 4 + c) * WPAD + j];
                Hbuf[((size_t)(bb + c) * T_ + t) * H_ + j] = (1.0f - z) * n + z * hp;
            }
        }

        // ---- 4-CTA barrier for this batch group ----
        __syncthreads();                      // all epilogue STGs issued
        if (tid == 0) {
            __threadfence();                  // release h_t to gpu scope
            atomicAdd(ctr, 1u);
            unsigned int target = 4u * (unsigned int)(t + 1);
            while (ldacq(ctr) < target) __nanosleep(64);
        }
        __syncthreads();                      // release whole CTA
    }
}

// ---------------- BN stats: deterministic two-pass ----------------
__global__ __launch_bounds__(256) void k_stats() {
    int ch = threadIdx.x;
    size_t r0 = (size_t)blockIdx.x * 256;
    const float* p = g_H2 + r0 * H_ + ch;
    float s = 0.f, s2 = 0.f;
    for (int r = 0; r < 256; r++) {
        float v = p[(size_t)r * H_];
        s += v;
        s2 = fmaf(v, v, s2);
    }
    g_part[(size_t)blockIdx.x * 512 + ch] = s;
    g_part[(size_t)blockIdx.x * 512 + 256 + ch] = s2;
}

__global__ __launch_bounds__(512) void k_stats_final() {
    int i = threadIdx.x;
    float acc = 0.f;
    for (int b = 0; b < 512; b++) acc += g_part[(size_t)b * 512 + i];
    g_bnsum[i] = acc;
}

// ---------------- normalize + hardtanh + temporal mean ----------------
__global__ __launch_bounds__(256) void k_summary(const float* __restrict__ gamma,
                                                 const float* __restrict__ beta) {
    int ch = threadIdx.x;
    int b = blockIdx.x;
    const float inv_bt = 1.0f / (float)BT_;
    float mean = g_bnsum[ch] * inv_bt;
    float var = g_bnsum[256 + ch] * inv_bt - mean * mean;
    float rstd = rsqrtf(var + EPS_);
    float scale = gamma[ch] * rstd;
    float shift = beta[ch] - mean * scale;

    const float* p = g_H2 + (size_t)b * T_ * H_ + ch;
    float acc = 0.f;
    for (int t = 0; t < T_; t++) {
        float v = fmaf(p[(size_t)t * H_], scale, shift);
        v = fminf(2.0f, fmaxf(-2.0f, v));
        acc += v;
    }
    g_sum[b * H_ + ch] = acc * (1.0f / (float)T_);
}

// ---------------- final FC ----------------
__global__ __launch_bounds__(128) void k_fc(const float* __restrict__ fc_w,
                                            const float* __restrict__ fc_b,
                                            float* __restrict__ out) {
    __shared__ float s[256];
    int o = threadIdx.x;
    int b = blockIdx.x;
    s[o] = g_sum[b * H_ + o];
    s[o + 128] = g_sum[b * H_ + o + 128];
    __syncthreads();
    float acc = fc_b[o];
    const float* w = fc_w + (size_t)o * H_;
#pragma unroll 8
    for (int ch = 0; ch < H_; ch++) acc = fmaf(s[ch], w[ch], acc);
    out[b * OUT_ + o] = acc;
}

// ---------------- launch ----------------
extern "C" void kernel_launch(void* const* d_in, const int* in_sizes, int n_in,
                              void* d_out, int out_size) {
    const float* x     = (const float*)d_in[0];
    const float* w_ih1 = (const float*)d_in[1];
    const float* w_hh1 = (const float*)d_in[2];
    const float* b_ih1 = (const float*)d_in[3];
    const float* b_hh1 = (const float*)d_in[4];
    const float* w_ih2 = (const float*)d_in[5];
    const float* w_hh2 = (const float*)d_in[6];
    const float* b_ih2 = (const float*)d_in[7];
    const float* b_hh2 = (const float*)d_in[8];
    const float* gamma = (const float*)d_in[9];
    const float* beta  = (const float*)d_in[10];
    const float* fc_w  = (const float*)d_in[11];
    const float* fc_b  = (const float*)d_in[12];
    float* out = (float*)d_out;

    static int smem_set = 0;
    if (!smem_set) {
        cudaFuncSetAttribute(k_recur<1>, cudaFuncAttributeMaxDynamicSharedMemorySize,
                             (int)SMEM_RECUR);
        cudaFuncSetAttribute(k_recur<2>, cudaFuncAttributeMaxDynamicSharedMemorySize,
                             (int)SMEM_RECUR);
        smem_set = 1;
    }

    dim3 gemm_grid(BT_ / 128, G3_ / 64);
    dim3 rec_grid(B_ / 8, H_ / 64);          // 32 x 4 = 128 CTAs, co-resident

    k_reset<<<1, 64>>>();
    k_gemm<0><<<gemm_grid, 256>>>(x, w_ih1, b_ih1, IN_);
    k_recur<1><<<rec_grid, 256, SMEM_RECUR>>>(w_hh1, b_hh1);
    k_gemm<1><<<gemm_grid, 256>>>(nullptr, w_ih2, b_ih2, H_);
    k_recur<2><<<rec_grid, 256, SMEM_RECUR>>>(w_hh2, b_hh2);

    k_stats<<<512, 256>>>();
    k_stats_final<<<1, 512>>>();
    k_summary<<<B_, 256>>>(gamma, beta);
    k_fc<<<B_, 128>>>(fc_w, fc_b, out);
}

// round 11
// speedup vs baseline: 1.0869x; 1.0869x over previous
#include <cuda_runtime.h>
#include <cuda_bf16.h>
#include <math.h>
#include <stdint.h>

#define B_   256
#define T_   512
#define IN_  128
#define H_   256
#define G3_  768          // 3*H
#define BT_  (B_ * T_)    // 131072
#define OUT_ 128
#define EPS_ 1e-5f

// ---------------- device-global scratch ----------------
__device__ float g_G [(size_t)BT_ * G3_];   // gi for current layer (reused)
__device__ float g_H1[(size_t)BT_ * H_];    // layer-1 hidden seq (b,t,h)
__device__ float g_H2[(size_t)BT_ * H_];    // layer-2 hidden seq (b,t,h)
__device__ float g_part[512 * 512];         // BN partial sums
__device__ float g_bnsum[2 * H_];
__device__ float g_sum[B_ * H_];
__device__ unsigned int g_ctr[2][32];       // per-layer, per-batch-group barrier counters

// ---------------- activations ----------------
__device__ __forceinline__ float fexp2a(float x) {
    float y;
    asm("ex2.approx.f32 %0, %1;" : "=f"(y) : "f"(x));
    return y;
}
__device__ __forceinline__ float fsigmoid(float x) {
    return 1.0f / (1.0f + fexp2a(-1.4426950408889634f * x));
}
__device__ __forceinline__ float ftanh(float x) {
    float e = fexp2a(2.8853900817779268f * x);
    return 1.0f - 2.0f / (e + 1.0f);
}
__device__ __forceinline__ unsigned int ldacq(const unsigned int* p) {
    unsigned int v;
    asm volatile("ld.acquire.gpu.u32 %0, [%1];" : "=r"(v) : "l"(p));
    return v;
}
__device__ __forceinline__ uint32_t smem_u32(const void* p) {
    uint32_t a;
    asm("{ .reg .u64 t; cvta.to.shared.u64 t, %1; cvt.u32.u64 %0, t; }" : "=r"(a) : "l"(p));
    return a;
}

// ---------------- counter reset ----------------
__global__ void k_reset() {
    ((unsigned int*)g_ctr)[threadIdx.x] = 0u;   // 64 threads
}

// ---------------- split-bf16 tensor-core GEMM (mma.sync, STATIC smem) ----------------
// g_G[m,n] = sum_k (Ah+Al)[m,k]*(Wh+Wl)[n,k] + bias[n]  (Al*Wl dropped, ~2^-18 rel)
// CTA tile M=128 x N=64, 8 warps (4m x 2n), K chunked by 32, fused fp32->bf16 split.
// SRC: 0 -> A = kernel parameter; 1 -> A = g_H1 (bound in DEVICE code -- host-side
// references to __device__ globals silently resolve to the host shadow via ATS!).
#define WSTR 40   // bf16 elems per row (80 B: 16B-aligned rows)

__device__ __forceinline__ void ldm_x4(uint32_t a, uint32_t* r) {
    asm volatile("ldmatrix.sync.aligned.m8n8.x4.shared.b16 {%0,%1,%2,%3}, [%4];"
                 : "=r"(r[0]), "=r"(r[1]), "=r"(r[2]), "=r"(r[3]) : "r"(a));
}
__device__ __forceinline__ void mma16816(float* c, const uint32_t* a, uint32_t b0, uint32_t b1) {
    asm volatile(
        "mma.sync.aligned.m16n8k16.row.col.f32.bf16.bf16.f32 "
        "{%0,%1,%2,%3}, {%4,%5,%6,%7}, {%8,%9}, {%0,%1,%2,%3};"
        : "+f"(c[0]), "+f"(c[1]), "+f"(c[2]), "+f"(c[3])
        : "r"(a[0]), "r"(a[1]), "r"(a[2]), "r"(a[3]), "r"(b0), "r"(b1));
}
__device__ __forceinline__ void cvt_split(float v, __nv_bfloat16& h, __nv_bfloat16& l) {
    h = __float2bfloat16(v);
    l = __float2bfloat16(v - __bfloat162float(h));
}

template <int K, int SRC>
__global__ __launch_bounds__(256) void k_mma(const float* __restrict__ Ain,
                                             const float* __restrict__ W,
                                             const float* __restrict__ bias) {
    const float* A = (SRC == 0) ? Ain : (const float*)g_H1;   // device-side binding!

    __shared__ __nv_bfloat16 sAh[128 * WSTR];
    __shared__ __nv_bfloat16 sAl[128 * WSTR];
    __shared__ __nv_bfloat16 sWh[64 * WSTR];
    __shared__ __nv_bfloat16 sWl[64 * WSTR];

    const int tid = threadIdx.x;
    const int lane = tid & 31;
    const int wid = tid >> 5;
    const int wm = wid >> 1;                     // 0..3
    const int wn = wid & 1;                      // 0..1
    const int n0 = blockIdx.x * 64;
    const int m0 = blockIdx.y * 128;

    float acc[2][4][4];
#pragma unroll
    for (int mi = 0; mi < 2; mi++)
#pragma unroll
        for (int ni = 0; ni < 4; ni++)
#pragma unroll
            for (int e = 0; e < 4; e++) acc[mi][ni][e] = 0.0f;

    const int arow = (lane & 15);
    const int acol = (lane >> 4) * 8;

    for (int k0 = 0; k0 < K; k0 += 32) {
        // ---- stage A chunk (128x32 fp32 -> split bf16): 1024 float4, 4/thread ----
#pragma unroll
        for (int i = 0; i < 4; i++) {
            int lin = tid + i * 256;
            int row = lin >> 3, qc = lin & 7;
            float4 v = *(const float4*)(A + (size_t)(m0 + row) * K + k0 + qc * 4);
            __nv_bfloat16 hx, lx, hy, ly, hz, lz, hw, lw;
            cvt_split(v.x, hx, lx); cvt_split(v.y, hy, ly);
            cvt_split(v.z, hz, lz); cvt_split(v.w, hw, lw);
            __nv_bfloat162 p;
            p.x = hx; p.y = hy; *(__nv_bfloat162*)(sAh + row * WSTR + qc * 4) = p;
            p.x = hz; p.y = hw; *(__nv_bfloat162*)(sAh + row * WSTR + qc * 4 + 2) = p;
            p.x = lx; p.y = ly; *(__nv_bfloat162*)(sAl + row * WSTR + qc * 4) = p;
            p.x = lz; p.y = lw; *(__nv_bfloat162*)(sAl + row * WSTR + qc * 4 + 2) = p;
        }
        // ---- stage W chunk (64x32): 512 float4, 2/thread ----
#pragma unroll
        for (int i = 0; i < 2; i++) {
            int lin = tid + i * 256;
            int row = lin >> 3, qc = lin & 7;
            float4 v = *(const float4*)(W + (size_t)(n0 + row) * K + k0 + qc * 4);
            __nv_bfloat16 hx, lx, hy, ly, hz, lz, hw, lw;
            cvt_split(v.x, hx, lx); cvt_split(v.y, hy, ly);
            cvt_split(v.z, hz, lz); cvt_split(v.w, hw, lw);
            __nv_bfloat162 p;
            p.x = hx; p.y = hy; *(__nv_bfloat162*)(sWh + row * WSTR + qc * 4) = p;
            p.x = hz; p.y = hw; *(__nv_bfloat162*)(sWh + row * WSTR + qc * 4 + 2) = p;
            p.x = lx; p.y = ly; *(__nv_bfloat162*)(sWl + row * WSTR + qc * 4) = p;
            p.x = lz; p.y = lw; *(__nv_bfloat162*)(sWl + row * WSTR + qc * 4 + 2) = p;
        }
        __syncthreads();

#pragma unroll
        for (int ks = 0; ks < 2; ks++) {
            const int kk = ks * 16;
            uint32_t ah[2][4], al[2][4], bh[2][4], bl[2][4];
#pragma unroll
            for (int mi = 0; mi < 2; mi++) {
                int r = wm * 32 + mi * 16 + arow;
                ldm_x4(smem_u32(sAh + r * WSTR + kk + acol), ah[mi]);
                ldm_x4(smem_u32(sAl + r * WSTR + kk + acol), al[mi]);
            }
#pragma unroll
            for (int ng = 0; ng < 2; ng++) {
                int r = wn * 32 + ng * 16 + arow;
                ldm_x4(smem_u32(sWh + r * WSTR + kk + acol), bh[ng]);
                ldm_x4(smem_u32(sWl + r * WSTR + kk + acol), bl[ng]);
            }
#pragma unroll
            for (int mi = 0; mi < 2; mi++)
#pragma unroll
                for (int ng = 0; ng < 2; ng++)
#pragma unroll
                    for (int s = 0; s < 2; s++) {
                        int ni = 2 * ng + s;
                        mma16816(acc[mi][ni], ah[mi], bh[ng][s], bh[ng][s + 2]);
                        mma16816(acc[mi][ni], ah[mi], bl[ng][s], bl[ng][s + 2]);
                        mma16816(acc[mi][ni], al[mi], bh[ng][s], bh[ng][s + 2]);
                    }
        }
        __syncthreads();
    }

    // ---- epilogue: bias add, store ----
#pragma unroll
    for (int mi = 0; mi < 2; mi++)
#pragma unroll
        for (int ni = 0; ni < 4; ni++) {
            int m = m0 + wm * 32 + mi * 16 + (lane >> 2);
            int n = n0 + wn * 32 + ni * 8 + (lane & 3) * 2;
            float b0 = bias[n], b1 = bias[n + 1];
            float2 v0 = make_float2(acc[mi][ni][0] + b0, acc[mi][ni][1] + b1);
            float2 v1 = make_float2(acc[mi][ni][2] + b0, acc[mi][ni][3] + b1);
            *(float2*)(g_G + (size_t)m * G3_ + n) = v0;
            *(float2*)(g_G + (size_t)(m + 8) * G3_ + n) = v1;
        }
}

// ---------------- persistent GRU recurrence (R3-proven atomic barrier) ----------------
#define WPAD 260
#define SMEM_RECUR ((3 * 64 * WPAD + 8 * WPAD) * sizeof(float))

template <int LAYER>
__global__ __launch_bounds__(256) void k_recur(const float* __restrict__ whh,
                                               const float* __restrict__ bhh) {
    extern __shared__ float smemf[];
    float* w_s = smemf;                      // [3][64][WPAD]
    float* h_s = smemf + 3 * 64 * WPAD;      // [8][WPAD]

    float* Hbuf = (LAYER == 1) ? g_H1 : g_H2;
    unsigned int* ctr = &g_ctr[LAYER - 1][blockIdx.x];

    const int tid = threadIdx.x;
    const int bg = blockIdx.x;
    const int j0 = blockIdx.y * 64;

    for (int lin = tid; lin < 3 * 64 * 64; lin += 256) {
        int g  = lin / (64 * 64);
        int r  = lin - g * 64 * 64;
        int jl = r >> 6;
        int q  = r & 63;
        float4 v = *(const float4*)(whh + (size_t)(g * 256 + j0 + jl) * H_ + 4 * q);
        *(float4*)(w_s + (g * 64 + jl) * WPAD + 4 * q) = v;
    }

    const int jl = tid >> 2;
    const int b2 = (tid >> 1) & 1;
    const int ks = tid & 1;
    const int j  = j0 + jl;
    const int bb = bg * 8 + b2 * 4;

    const float br = bhh[j], bz = bhh[j + 256], bn = bhh[j + 512];

    const float* wr  = w_s + (0 * 64 + jl) * WPAD;
    const float* wzp = w_s + (1 * 64 + jl) * WPAD;
    const float* wnp = w_s + (2 * 64 + jl) * WPAD;

    __syncthreads();

    for (int t = 0; t < T_; t++) {
        float gir[4], giz[4], gin[4];
        if (ks == 0) {
#pragma unroll
            for (int c = 0; c < 4; c++) {
                size_t base = ((size_t)(bb + c) * T_ + t) * G3_ + j;
                gir[c] = g_G[base];
                giz[c] = g_G[base + 256];
                gin[c] = g_G[base + 512];
            }
        }

        if (t == 0) {
#pragma unroll
            for (int lin = tid; lin < 512; lin += 256) {
                int b = lin >> 6, q = lin & 63;
                *(float4*)(h_s + b * WPAD + 4 * q) = make_float4(0.f, 0.f, 0.f, 0.f);
            }
        } else {
#pragma unroll
            for (int lin = tid; lin < 512; lin += 256) {
                int b = lin >> 6, q = lin & 63;
                float4 v = *(const float4*)(Hbuf +
                    ((size_t)(bg * 8 + b) * T_ + (t - 1)) * H_ + 4 * q);
                *(float4*)(h_s + b * WPAD + 4 * q) = v;
            }
        }
        __syncthreads();

        float ar[4] = {0.f, 0.f, 0.f, 0.f};
        float az[4] = {0.f, 0.f, 0.f, 0.f};
        float an[4] = {0.f, 0.f, 0.f, 0.f};

#pragma unroll 4
        for (int i = 0; i < 32; i++) {
            int q = ((i + 4 * ks) & 31) + 32 * ks;
            float4 w_r = *(const float4*)(wr  + 4 * q);
            float4 w_z = *(const float4*)(wzp + 4 * q);
            float4 w_n = *(const float4*)(wnp + 4 * q);
#pragma unroll
            for (int c = 0; c < 4; c++) {
                float4 hv = *(const float4*)(h_s + (b2 * 4 + c) * WPAD + 4 * q);
                ar[c] = fmaf(hv.x, w_r.x, ar[c]); ar[c] = fmaf(hv.y, w_r.y, ar[c]);
                ar[c] = fmaf(hv.z, w_r.z, ar[c]); ar[c] = fmaf(hv.w, w_r.w, ar[c]);
                az[c] = fmaf(hv.x, w_z.x, az[c]); az[c] = fmaf(hv.y, w_z.y, az[c]);
                az[c] = fmaf(hv.z, w_z.z, az[c]); az[c] = fmaf(hv.w, w_z.w, az[c]);
                an[c] = fmaf(hv.x, w_n.x, an[c]); an[c] = fmaf(hv.y, w_n.y, an[c]);
                an[c] = fmaf(hv.z, w_n.z, an[c]); an[c] = fmaf(hv.w, w_n.w, an[c]);
            }
        }

#pragma unroll
        for (int c = 0; c < 4; c++) {
            ar[c] += __shfl_xor_sync(0xffffffffu, ar[c], 1);
            az[c] += __shfl_xor_sync(0xffffffffu, az[c], 1);
            an[c] += __shfl_xor_sync(0xffffffffu, an[c], 1);
        }

        if (ks == 0) {
#pragma unroll
            for (int c = 0; c < 4; c++) {
                float r = fsigmoid(gir[c] + ar[c] + br);
                float z = fsigmoid(giz[c] + az[c] + bz);
                float n = ftanh   (gin[c] + r * (an[c] + bn));
                float hp = h_s[(b2 * 4 + c) * WPAD + j];
                Hbuf[((size_t)(bb + c) * T_ + t) * H_ + j] = (1.0f - z) * n + z * hp;
            }
        }

        __syncthreads();
        if (tid == 0) {
            __threadfence();
            atomicAdd(ctr, 1u);
            unsigned int target = 4u * (unsigned int)(t + 1);
            while (ldacq(ctr) < target) __nanosleep(64);
        }
        __syncthreads();
    }
}

// ---------------- BN stats ----------------
__global__ __launch_bounds__(256) void k_stats() {
    int ch = threadIdx.x;
    size_t r0 = (size_t)blockIdx.x * 256;
    const float* p = g_H2 + r0 * H_ + ch;
    float s = 0.f, s2 = 0.f;
    for (int r = 0; r < 256; r++) {
        float v = p[(size_t)r * H_];
        s += v;
        s2 = fmaf(v, v, s2);
    }
    g_part[(size_t)blockIdx.x * 512 + ch] = s;
    g_part[(size_t)blockIdx.x * 512 + 256 + ch] = s2;
}

__global__ __launch_bounds__(512) void k_stats_final() {
    int i = threadIdx.x;
    float acc = 0.f;
    for (int b = 0; b < 512; b++) acc += g_part[(size_t)b * 512 + i];
    g_bnsum[i] = acc;
}

// ---------------- normalize + hardtanh + temporal mean ----------------
__global__ __launch_bounds__(256) void k_summary(const float* __restrict__ gamma,
                                                 const float* __restrict__ beta) {
    int ch = threadIdx.x;
    int b = blockIdx.x;
    const float inv_bt = 1.0f / (float)BT_;
    float mean = g_bnsum[ch] * inv_bt;
    float var = g_bnsum[256 + ch] * inv_bt - mean * mean;
    float rstd = rsqrtf(var + EPS_);
    float scale = gamma[ch] * rstd;
    float shift = beta[ch] - mean * scale;

    const float* p = g_H2 + (size_t)b * T_ * H_ + ch;
    float acc = 0.f;
    for (int t = 0; t < T_; t++) {
        float v = fmaf(p[(size_t)t * H_], scale, shift);
        v = fminf(2.0f, fmaxf(-2.0f, v));
        acc += v;
    }
    g_sum[b * H_ + ch] = acc * (1.0f / (float)T_);
}

// ---------------- final FC ----------------
__global__ __launch_bounds__(128) void k_fc(const float* __restrict__ fc_w,
                                            const float* __restrict__ fc_b,
                                            float* __restrict__ out) {
    __shared__ float s[256];
    int o = threadIdx.x;
    int b = blockIdx.x;
    s[o] = g_sum[b * H_ + o];
    s[o + 128] = g_sum[b * H_ + o + 128];
    __syncthreads();
    float acc = fc_b[o];
    const float* w = fc_w + (size_t)o * H_;
#pragma unroll 8
    for (int ch = 0; ch < H_; ch++) acc = fmaf(s[ch], w[ch], acc);
    out[b * OUT_ + o] = acc;
}

// ---------------- launch ----------------
extern "C" void kernel_launch(void* const* d_in, const int* in_sizes, int n_in,
                              void* d_out, int out_size) {
    const float* x     = (const float*)d_in[0];
    const float* w_ih1 = (const float*)d_in[1];
    const float* w_hh1 = (const float*)d_in[2];
    const float* b_ih1 = (const float*)d_in[3];
    const float* b_hh1 = (const float*)d_in[4];
    const float* w_ih2 = (const float*)d_in[5];
    const float* w_hh2 = (const float*)d_in[6];
    const float* b_ih2 = (const float*)d_in[7];
    const float* b_hh2 = (const float*)d_in[8];
    const float* gamma = (const float*)d_in[9];
    const float* beta  = (const float*)d_in[10];
    const float* fc_w  = (const float*)d_in[11];
    const float* fc_b  = (const float*)d_in[12];
    float* out = (float*)d_out;

    cudaFuncSetAttribute(k_recur<1>, cudaFuncAttributeMaxDynamicSharedMemorySize, (int)SMEM_RECUR);
    cudaFuncSetAttribute(k_recur<2>, cudaFuncAttributeMaxDynamicSharedMemorySize, (int)SMEM_RECUR);

    dim3 mma_grid(G3_ / 64, BT_ / 128);      // (12, 1024): n-fastest for A L2 reuse
    dim3 rec_grid(B_ / 8, H_ / 64);          // (32, 4)

    k_reset<<<1, 64>>>();
    k_mma<128, 0><<<mma_grid, 256>>>(x, w_ih1, b_ih1);
    k_recur<1><<<rec_grid, 256, SMEM_RECUR>>>(w_hh1, b_hh1);
    k_mma<256, 1><<<mma_grid, 256>>>(nullptr, w_ih2, b_ih2);
    k_recur<2><<<rec_grid, 256, SMEM_RECUR>>>(w_hh2, b_hh2);

    k_stats<<<512, 256>>>();
    k_stats_final<<<1, 512>>>();
    k_summary<<<B_, 256>>>(gamma, beta);
    k_fc<<<B_, 128>>>(fc_w, fc_b, out);
}

// round 13
// speedup vs baseline: 1.3603x; 1.2516x over previous
#include <cuda_runtime.h>
#include <cuda_bf16.h>
#include <math.h>
#include <stdint.h>
#include <string.h>

#define B_   256
#define T_   512
#define IN_  128
#define H_   256
#define G3_  768          // 3*H
#define BT_  (B_ * T_)    // 131072
#define OUT_ 128
#define EPS_ 1e-5f

// ---------------- device-global scratch ----------------
__device__ float g_G [(size_t)BT_ * G3_];   // gi for current layer (reused)
__device__ float g_H1[(size_t)BT_ * H_];    // layer-1 hidden seq (b,t,h)
__device__ float g_H2[(size_t)BT_ * H_];    // layer-2 hidden seq (b,t,h)
__device__ uint32_t g_Hbits[B_ * H_];       // h as packed (bf16 hi<<16 | bf16 lo)
__device__ float g_part[512 * 512];         // BN partial sums
__device__ float g_bnsum[2 * H_];
__device__ float g_sum[B_ * H_];
__device__ unsigned int g_ctr[2][32];       // per-layer, per-batch-group barrier counters

// ---------------- activations / helpers ----------------
__device__ __forceinline__ float fexp2a(float x) {
    float y;
    asm("ex2.approx.f32 %0, %1;" : "=f"(y) : "f"(x));
    return y;
}
__device__ __forceinline__ float fsigmoid(float x) {
    return 1.0f / (1.0f + fexp2a(-1.4426950408889634f * x));
}
__device__ __forceinline__ float ftanh(float x) {
    float e = fexp2a(2.8853900817779268f * x);
    return 1.0f - 2.0f / (e + 1.0f);
}
__device__ __forceinline__ unsigned int ldacq(const unsigned int* p) {
    unsigned int v;
    asm volatile("ld.acquire.gpu.u32 %0, [%1];" : "=r"(v) : "l"(p));
    return v;
}
__device__ __forceinline__ uint32_t smem_u32(const void* p) {
    uint32_t a;
    asm("{ .reg .u64 t; cvta.to.shared.u64 t, %1; cvt.u32.u64 %0, t; }" : "=r"(a) : "l"(p));
    return a;
}
__device__ __forceinline__ void ldm_x4(uint32_t a, uint32_t* r) {
    asm volatile("ldmatrix.sync.aligned.m8n8.x4.shared.b16 {%0,%1,%2,%3}, [%4];"
                 : "=r"(r[0]), "=r"(r[1]), "=r"(r[2]), "=r"(r[3]) : "r"(a));
}
__device__ __forceinline__ void ldm_x2(uint32_t a, uint32_t* r) {
    asm volatile("ldmatrix.sync.aligned.m8n8.x2.shared.b16 {%0,%1}, [%2];"
                 : "=r"(r[0]), "=r"(r[1]) : "r"(a));
}
__device__ __forceinline__ void mma16816(float* c, const uint32_t* a, uint32_t b0, uint32_t b1) {
    asm volatile(
        "mma.sync.aligned.m16n8k16.row.col.f32.bf16.bf16.f32 "
        "{%0,%1,%2,%3}, {%4,%5,%6,%7}, {%8,%9}, {%0,%1,%2,%3};"
        : "+f"(c[0]), "+f"(c[1]), "+f"(c[2]), "+f"(c[3])
        : "r"(a[0]), "r"(a[1]), "r"(a[2]), "r"(a[3]), "r"(b0), "r"(b1));
}
__device__ __forceinline__ void cvt_split(float v, __nv_bfloat16& h, __nv_bfloat16& l) {
    h = __float2bfloat16(v);
    l = __float2bfloat16(v - __bfloat162float(h));
}
__device__ __forceinline__ uint16_t bfbits(__nv_bfloat16 b) {
    uint16_t u; memcpy(&u, &b, 2); return u;
}

// ---------------- counter reset ----------------
__global__ void k_reset() {
    ((unsigned int*)g_ctr)[threadIdx.x] = 0u;   // 64 threads
}

// ---------------- split-bf16 tensor-core GEMM (unchanged, verified) ----------------
#define WSTR 40   // bf16 elems per row (80 B)

template <int K, int SRC>
__global__ __launch_bounds__(256) void k_mma(const float* __restrict__ Ain,
                                             const float* __restrict__ W,
                                             const float* __restrict__ bias) {
    const float* A = (SRC == 0) ? Ain : (const float*)g_H1;   // device-side binding!

    __shared__ __nv_bfloat16 sAh[128 * WSTR];
    __shared__ __nv_bfloat16 sAl[128 * WSTR];
    __shared__ __nv_bfloat16 sWh[64 * WSTR];
    __shared__ __nv_bfloat16 sWl[64 * WSTR];

    const int tid = threadIdx.x;
    const int lane = tid & 31;
    const int wid = tid >> 5;
    const int wm = wid >> 1;
    const int wn = wid & 1;
    const int n0 = blockIdx.x * 64;
    const int m0 = blockIdx.y * 128;

    float acc[2][4][4];
#pragma unroll
    for (int mi = 0; mi < 2; mi++)
#pragma unroll
        for (int ni = 0; ni < 4; ni++)
#pragma unroll
            for (int e = 0; e < 4; e++) acc[mi][ni][e] = 0.0f;

    const int arow = (lane & 15);
    const int acol = (lane >> 4) * 8;

    for (int k0 = 0; k0 < K; k0 += 32) {
#pragma unroll
        for (int i = 0; i < 4; i++) {
            int lin = tid + i * 256;
            int row = lin >> 3, qc = lin & 7;
            float4 v = *(const float4*)(A + (size_t)(m0 + row) * K + k0 + qc * 4);
            __nv_bfloat16 hx, lx, hy, ly, hz, lz, hw, lw;
            cvt_split(v.x, hx, lx); cvt_split(v.y, hy, ly);
            cvt_split(v.z, hz, lz); cvt_split(v.w, hw, lw);
            __nv_bfloat162 p;
            p.x = hx; p.y = hy; *(__nv_bfloat162*)(sAh + row * WSTR + qc * 4) = p;
            p.x = hz; p.y = hw; *(__nv_bfloat162*)(sAh + row * WSTR + qc * 4 + 2) = p;
            p.x = lx; p.y = ly; *(__nv_bfloat162*)(sAl + row * WSTR + qc * 4) = p;
            p.x = lz; p.y = lw; *(__nv_bfloat162*)(sAl + row * WSTR + qc * 4 + 2) = p;
        }
#pragma unroll
        for (int i = 0; i < 2; i++) {
            int lin = tid + i * 256;
            int row = lin >> 3, qc = lin & 7;
            float4 v = *(const float4*)(W + (size_t)(n0 + row) * K + k0 + qc * 4);
            __nv_bfloat16 hx, lx, hy, ly, hz, lz, hw, lw;
            cvt_split(v.x, hx, lx); cvt_split(v.y, hy, ly);
            cvt_split(v.z, hz, lz); cvt_split(v.w, hw, lw);
            __nv_bfloat162 p;
            p.x = hx; p.y = hy; *(__nv_bfloat162*)(sWh + row * WSTR + qc * 4) = p;
            p.x = hz; p.y = hw; *(__nv_bfloat162*)(sWh + row * WSTR + qc * 4 + 2) = p;
            p.x = lx; p.y = ly; *(__nv_bfloat162*)(sWl + row * WSTR + qc * 4) = p;
            p.x = lz; p.y = lw; *(__nv_bfloat162*)(sWl + row * WSTR + qc * 4 + 2) = p;
        }
        __syncthreads();

#pragma unroll
        for (int ks = 0; ks < 2; ks++) {
            const int kk = ks * 16;
            uint32_t ah[2][4], al[2][4], bh[2][4], bl[2][4];
#pragma unroll
            for (int mi = 0; mi < 2; mi++) {
                int r = wm * 32 + mi * 16 + arow;
                ldm_x4(smem_u32(sAh + r * WSTR + kk + acol), ah[mi]);
                ldm_x4(smem_u32(sAl + r * WSTR + kk + acol), al[mi]);
            }
#pragma unroll
            for (int ng = 0; ng < 2; ng++) {
                int r = wn * 32 + ng * 16 + arow;
                ldm_x4(smem_u32(sWh + r * WSTR + kk + acol), bh[ng]);
                ldm_x4(smem_u32(sWl + r * WSTR + kk + acol), bl[ng]);
            }
#pragma unroll
            for (int mi = 0; mi < 2; mi++)
#pragma unroll
                for (int ng = 0; ng < 2; ng++)
#pragma unroll
                    for (int s = 0; s < 2; s++) {
                        int ni = 2 * ng + s;
                        mma16816(acc[mi][ni], ah[mi], bh[ng][s], bh[ng][s + 2]);
                        mma16816(acc[mi][ni], ah[mi], bl[ng][s], bl[ng][s + 2]);
                        mma16816(acc[mi][ni], al[mi], bh[ng][s], bh[ng][s + 2]);
                    }
        }
        __syncthreads();
    }

#pragma unroll
    for (int mi = 0; mi < 2; mi++)
#pragma unroll
        for (int ni = 0; ni < 4; ni++) {
            int m = m0 + wm * 32 + mi * 16 + (lane >> 2);
            int n = n0 + wn * 32 + ni * 8 + (lane & 3) * 2;
            float b0 = bias[n], b1 = bias[n + 1];
            float2 v0 = make_float2(acc[mi][ni][0] + b0, acc[mi][ni][1] + b1);
            float2 v1 = make_float2(acc[mi][ni][2] + b0, acc[mi][ni][3] + b1);
            *(float2*)(g_G + (size_t)m * G3_ + n) = v0;
            *(float2*)(g_G + (size_t)(m + 8) * G3_ + n) = v1;
        }
}

// ---------------- tensor-core GRU recurrence ----------------
// grid (16 batch-groups, 4 feature-CTAs), 256 thr. Per CTA per step:
// gh[16 x 192] = h[16 x 256] @ Wslice[192 x 256]^T  via split-bf16 mma.sync.
// W rows ordered n = 3*f_local + gate  (warp w owns rows [24w,24w+24) = feats [8w,8w+8)).
#define WROW 264                          // bf16 elems per W/A row (528 B, conflict-free)
#define RW_BYTES (192 * WROW * 2)         // 101376
#define ROFF_WH 0
#define ROFF_WL RW_BYTES
#define ROFF_AH (2 * RW_BYTES)            // 202752
#define RA_BYTES (16 * WROW * 2)          // 8448
#define ROFF_AL (ROFF_AH + RA_BYTES)
#define ROFF_HOWN (ROFF_AH + 2 * RA_BYTES)            // 219648
#define SMEM_REC (ROFF_HOWN + 16 * 64 * 4)            // 223744

template <int LAYER>
__global__ __launch_bounds__(256) void k_recur(const float* __restrict__ whh,
                                               const float* __restrict__ bhh) {
    extern __shared__ char sm8[];
    float* Hbuf = (LAYER == 1) ? g_H1 : g_H2;
    unsigned int* ctr = &g_ctr[LAYER - 1][blockIdx.x];

    const int tid = threadIdx.x, lane = tid & 31, wid = tid >> 5;
    const int bg = blockIdx.x;                  // 0..15
    const int j0 = blockIdx.y * 64;             // feature base
    const int bb0 = bg * 16;                    // batch base
    const uint32_t sb = smem_u32(sm8);
    float* h_own = (float*)(sm8 + ROFF_HOWN);   // [16][64] fp32, persistent
    float* gh    = (float*)(sm8 + ROFF_AH);     // [16][192] fp32, aliases A bufs

    // ---- stage W slice once: rows n = 3f+gate, fp32 -> split bf16 ----
    for (int lin = tid; lin < 192 * 64; lin += 256) {
        int n = lin >> 6, q = lin & 63;
        int f = n / 3, gate = n - 3 * f;
        float4 v = *(const float4*)(whh + (size_t)(gate * H_ + j0 + f) * H_ + 4 * q);
        __nv_bfloat16 hx, lx, hy, ly, hz, lz, hw, lw;
        cvt_split(v.x, hx, lx); cvt_split(v.y, hy, ly);
        cvt_split(v.z, hz, lz); cvt_split(v.w, hw, lw);
        __nv_bfloat162 p;
        __nv_bfloat16* wh = (__nv_bfloat16*)(sm8 + ROFF_WH) + n * WROW + 4 * q;
        __nv_bfloat16* wl = (__nv_bfloat16*)(sm8 + ROFF_WL) + n * WROW + 4 * q;
        p.x = hx; p.y = hy; *(__nv_bfloat162*)(wh) = p;
        p.x = hz; p.y = hw; *(__nv_bfloat162*)(wh + 2) = p;
        p.x = lx; p.y = ly; *(__nv_bfloat162*)(wl) = p;
        p.x = lz; p.y = lw; *(__nv_bfloat162*)(wl + 2) = p;
    }
    // zero persistent h_own
    for (int i = tid; i < 16 * 64; i += 256) h_own[i] = 0.0f;

    // per-thread roles
    const int f = tid & 63, bq = tid >> 6;      // recombine: feature f, batch quad bq
    const int j = j0 + f;
    const float br = bhh[j], bz = bhh[j + 256], bn = bhh[j + 512];

    const int nb = 24 * wid;                    // warp's first n-row
    const int arow = lane & 15, acol = (lane >> 4) * 8;
    const int xrow = nb + 16 + (lane & 7);      // ldsm x2 rows (tile 2)
    const int xcol = ((lane >> 3) & 1) * 8;

    __syncthreads();

    for (int t = 0; t < T_; t++) {
        // ---- prefetch gi (DRAM), consumed in recombine ----
        float gir[4], giz[4], gin[4];
#pragma unroll
        for (int c = 0; c < 4; c++) {
            int bl = bq * 4 + c;
            size_t base = ((size_t)(bb0 + bl) * T_ + t) * G3_ + j;
            gir[c] = g_G[base];
            giz[c] = g_G[base + 256];
            gin[c] = g_G[base + 512];
        }

        if (t > 0) {
            // ---- stage A: unpack g_Hbits -> sAh/sAl ----
            {
                int b = tid >> 4, ch = tid & 15;
                const uint32_t* src = g_Hbits + (size_t)(bb0 + b) * H_ + ch * 16;
                uint32_t dh = sb + ROFF_AH + (uint32_t)(b * WROW + ch * 16) * 2;
                uint32_t dl = sb + ROFF_AL + (uint32_t)(b * WROW + ch * 16) * 2;
#pragma unroll
                for (int i = 0; i < 16; i += 2) {
                    uint32_t v0 = src[i], v1 = src[i + 1];
                    uint32_t hi = __byte_perm(v0, v1, 0x7632);
                    uint32_t lo = __byte_perm(v0, v1, 0x5410);
                    asm volatile("st.shared.b32 [%0], %1;" :: "r"(dh + i * 2), "r"(hi) : "memory");
                    asm volatile("st.shared.b32 [%0], %1;" :: "r"(dl + i * 2), "r"(lo) : "memory");
                }
            }
            __syncthreads();

            // ---- MMA: gh = (Ah+Al)(Wh+Wl)^T, drop AlWl ----
            float acc[3][4];
#pragma unroll
            for (int ti = 0; ti < 3; ti++)
#pragma unroll
                for (int e = 0; e < 4; e++) acc[ti][e] = 0.0f;

#pragma unroll 4
            for (int kc = 0; kc < 16; kc++) {
                const int kk = kc * 16;
                uint32_t ah[4], al[4], wh4[4], wl4[4], wh2[2], wl2[2];
                ldm_x4(sb + ROFF_AH + (uint32_t)(arow * WROW + kk + acol) * 2, ah);
                ldm_x4(sb + ROFF_AL + (uint32_t)(arow * WROW + kk + acol) * 2, al);
                ldm_x4(sb + ROFF_WH + (uint32_t)((nb + arow) * WROW + kk + acol) * 2, wh4);
                ldm_x4(sb + ROFF_WL + (uint32_t)((nb + arow) * WROW + kk + acol) * 2, wl4);
                ldm_x2(sb + ROFF_WH + (uint32_t)(xrow * WROW + kk + xcol) * 2, wh2);
                ldm_x2(sb + ROFF_WL + (uint32_t)(xrow * WROW + kk + xcol) * 2, wl2);
                mma16816(acc[0], ah, wh4[0], wh4[2]);
                mma16816(acc[0], ah, wl4[0], wl4[2]);
                mma16816(acc[0], al, wh4[0], wh4[2]);
                mma16816(acc[1], ah, wh4[1], wh4[3]);
                mma16816(acc[1], ah, wl4[1], wl4[3]);
                mma16816(acc[1], al, wh4[1], wh4[3]);
                mma16816(acc[2], ah, wh2[0], wh2[1]);
                mma16816(acc[2], ah, wl2[0], wl2[1]);
                mma16816(acc[2], al, wh2[0], wh2[1]);
            }
            __syncthreads();   // all ldsm done before gh aliases A bufs

            // ---- c-frags -> gh smem ----
#pragma unroll
            for (int ti = 0; ti < 3; ti++) {
                int col = nb + 8 * ti + 2 * (lane & 3);
                int r0 = lane >> 2;
                *(float2*)&gh[r0 * 192 + col] = make_float2(acc[ti][0], acc[ti][1]);
                *(float2*)&gh[(r0 + 8) * 192 + col] = make_float2(acc[ti][2], acc[ti][3]);
            }
            __syncthreads();
        }

        // ---- recombine: gates -> h; store h_own, fp32 H, packed bits ----
#pragma unroll
        for (int c = 0; c < 4; c++) {
            int bl = bq * 4 + c;
            float ghr = 0.f, ghz = 0.f, ghn = 0.f;
            if (t > 0) {
                ghr = gh[bl * 192 + 3 * f];
                ghz = gh[bl * 192 + 3 * f + 1];
                ghn = gh[bl * 192 + 3 * f + 2];
            }
            float r = fsigmoid(gir[c] + ghr + br);
            float z = fsigmoid(giz[c] + ghz + bz);
            float n = ftanh(gin[c] + r * (ghn + bn));
            float hp = h_own[bl * 64 + f];
            float h = (1.0f - z) * n + z * hp;
            h_own[bl * 64 + f] = h;
            Hbuf[((size_t)(bb0 + bl) * T_ + t) * H_ + j] = h;
            __nv_bfloat16 hh, hl;
            cvt_split(h, hh, hl);
            g_Hbits[(size_t)(bb0 + bl) * H_ + j] =
                ((uint32_t)bfbits(hh) << 16) | (uint32_t)bfbits(hl);
        }

        // ---- 4-CTA barrier for this batch group ----
        __syncthreads();
        if (tid == 0) {
            __threadfence();
            atomicAdd(ctr, 1u);
            unsigned int target = 4u * (unsigned int)(t + 1);
            while (ldacq(ctr) < target) __nanosleep(64);
        }
        __syncthreads();
    }
}

// ---------------- BN stats ----------------
__global__ __launch_bounds__(256) void k_stats() {
    int ch = threadIdx.x;
    size_t r0 = (size_t)blockIdx.x * 256;
    const float* p = g_H2 + r0 * H_ + ch;
    float s = 0.f, s2 = 0.f;
    for (int r = 0; r < 256; r++) {
        float v = p[(size_t)r * H_];
        s += v;
        s2 = fmaf(v, v, s2);
    }
    g_part[(size_t)blockIdx.x * 512 + ch] = s;
    g_part[(size_t)blockIdx.x * 512 + 256 + ch] = s2;
}

__global__ __launch_bounds__(512) void k_stats_final() {
    int i = threadIdx.x;
    float acc = 0.f;
    for (int b = 0; b < 512; b++) acc += g_part[(size_t)b * 512 + i];
    g_bnsum[i] = acc;
}

// ---------------- normalize + hardtanh + temporal mean ----------------
__global__ __launch_bounds__(256) void k_summary(const float* __restrict__ gamma,
                                                 const float* __restrict__ beta) {
    int ch = threadIdx.x;
    int b = blockIdx.x;
    const float inv_bt = 1.0f / (float)BT_;
    float mean = g_bnsum[ch] * inv_bt;
    float var = g_bnsum[256 + ch] * inv_bt - mean * mean;
    float rstd = rsqrtf(var + EPS_);
    float scale = gamma[ch] * rstd;
    float shift = beta[ch] - mean * scale;

    const float* p = g_H2 + (size_t)b * T_ * H_ + ch;
    float acc = 0.f;
    for (int t = 0; t < T_; t++) {
        float v = fmaf(p[(size_t)t * H_], scale, shift);
        v = fminf(2.0f, fmaxf(-2.0f, v));
        acc += v;
    }
    g_sum[b * H_ + ch] = acc * (1.0f / (float)T_);
}

// ---------------- final FC ----------------
__global__ __launch_bounds__(128) void k_fc(const float* __restrict__ fc_w,
                                            const float* __restrict__ fc_b,
                                            float* __restrict__ out) {
    __shared__ float s[256];
    int o = threadIdx.x;
    int b = blockIdx.x;
    s[o] = g_sum[b * H_ + o];
    s[o + 128] = g_sum[b * H_ + o + 128];
    __syncthreads();
    float acc = fc_b[o];
    const float* w = fc_w + (size_t)o * H_;
#pragma unroll 8
    for (int ch = 0; ch < H_; ch++) acc = fmaf(s[ch], w[ch], acc);
    out[b * OUT_ + o] = acc;
}

// ---------------- launch ----------------
extern "C" void kernel_launch(void* const* d_in, const int* in_sizes, int n_in,
                              void* d_out, int out_size) {
    const float* x     = (const float*)d_in[0];
    const float* w_ih1 = (const float*)d_in[1];
    const float* w_hh1 = (const float*)d_in[2];
    const float* b_ih1 = (const float*)d_in[3];
    const float* b_hh1 = (const float*)d_in[4];
    const float* w_ih2 = (const float*)d_in[5];
    const float* w_hh2 = (const float*)d_in[6];
    const float* b_ih2 = (const float*)d_in[7];
    const float* b_hh2 = (const float*)d_in[8];
    const float* gamma = (const float*)d_in[9];
    const float* beta  = (const float*)d_in[10];
    const float* fc_w  = (const float*)d_in[11];
    const float* fc_b  = (const float*)d_in[12];
    float* out = (float*)d_out;

    cudaFuncSetAttribute(k_recur<1>, cudaFuncAttributeMaxDynamicSharedMemorySize, SMEM_REC);
    cudaFuncSetAttribute(k_recur<2>, cudaFuncAttributeMaxDynamicSharedMemorySize, SMEM_REC);

    dim3 mma_grid(G3_ / 64, BT_ / 128);      // (12, 1024)
    dim3 rec_grid(16, 4);                    // 16 batch-groups x 4 feature CTAs

    k_reset<<<1, 64>>>();
    k_mma<128, 0><<<mma_grid, 256>>>(x, w_ih1, b_ih1);
    k_recur<1><<<rec_grid, 256, SMEM_REC>>>(w_hh1, b_hh1);
    k_mma<256, 1><<<mma_grid, 256>>>(nullptr, w_ih2, b_ih2);
    k_recur<2><<<rec_grid, 256, SMEM_REC>>>(w_hh2, b_hh2);

    k_stats<<<512, 256>>>();
    k_stats_final<<<1, 512>>>();
    k_summary<<<B_, 256>>>(gamma, beta);
    k_fc<<<B_, 128>>>(fc_w, fc_b, out);
}

// round 14
// speedup vs baseline: 1.7982x; 1.3219x over previous
#include <cuda_runtime.h>
#include <cuda_bf16.h>
#include <math.h>
#include <stdint.h>
#include <string.h>

#define B_   256
#define T_   512
#define IN_  128
#define H_   256
#define G3_  768          // 3*H
#define BT_  (B_ * T_)    // 131072
#define OUT_ 128
#define EPS_ 1e-5f

// ---------------- device-global scratch ----------------
__device__ float g_G [(size_t)BT_ * G3_];   // gi for current layer (reused)
__device__ float g_H1[(size_t)BT_ * H_];    // layer-1 hidden seq (b,t,h)
__device__ float g_H2[(size_t)BT_ * H_];    // layer-2 hidden seq (b,t,h)
__device__ float g_part[512 * 512];         // BN partial sums
__device__ float g_bnsum[2 * H_];
__device__ float g_sum[B_ * H_];

// ---------------- activations / helpers ----------------
__device__ __forceinline__ float fexp2a(float x) {
    float y;
    asm("ex2.approx.f32 %0, %1;" : "=f"(y) : "f"(x));
    return y;
}
__device__ __forceinline__ float fsigmoid(float x) {
    return 1.0f / (1.0f + fexp2a(-1.4426950408889634f * x));
}
__device__ __forceinline__ float ftanh(float x) {
    float e = fexp2a(2.8853900817779268f * x);
    return 1.0f - 2.0f / (e + 1.0f);
}
__device__ __forceinline__ uint32_t smem_u32(const void* p) {
    uint32_t a;
    asm("{ .reg .u64 t; cvta.to.shared.u64 t, %1; cvt.u32.u64 %0, t; }" : "=r"(a) : "l"(p));
    return a;
}
__device__ __forceinline__ void ldm_x4(uint32_t a, uint32_t* r) {
    asm volatile("ldmatrix.sync.aligned.m8n8.x4.shared.b16 {%0,%1,%2,%3}, [%4];"
                 : "=r"(r[0]), "=r"(r[1]), "=r"(r[2]), "=r"(r[3]) : "r"(a));
}
__device__ __forceinline__ void ldm_x2(uint32_t a, uint32_t* r) {
    asm volatile("ldmatrix.sync.aligned.m8n8.x2.shared.b16 {%0,%1}, [%2];"
                 : "=r"(r[0]), "=r"(r[1]) : "r"(a));
}
__device__ __forceinline__ void mma16816(float* c, const uint32_t* a, uint32_t b0, uint32_t b1) {
    asm volatile(
        "mma.sync.aligned.m16n8k16.row.col.f32.bf16.bf16.f32 "
        "{%0,%1,%2,%3}, {%4,%5,%6,%7}, {%8,%9}, {%0,%1,%2,%3};"
        : "+f"(c[0]), "+f"(c[1]), "+f"(c[2]), "+f"(c[3])
        : "r"(a[0]), "r"(a[1]), "r"(a[2]), "r"(a[3]), "r"(b0), "r"(b1));
}
__device__ __forceinline__ void cvt_split(float v, __nv_bfloat16& h, __nv_bfloat16& l) {
    h = __float2bfloat16(v);
    l = __float2bfloat16(v - __bfloat162float(h));
}
__device__ __forceinline__ uint16_t bfbits(__nv_bfloat16 b) {
    uint16_t u; memcpy(&u, &b, 2); return u;
}

// ---------------- split-bf16 tensor-core GEMM (unchanged, verified) ----------------
#define WSTR 40   // bf16 elems per row (80 B)

template <int K, int SRC>
__global__ __launch_bounds__(256) void k_mma(const float* __restrict__ Ain,
                                             const float* __restrict__ W,
                                             const float* __restrict__ bias) {
    const float* A = (SRC == 0) ? Ain : (const float*)g_H1;   // device-side binding!

    __shared__ __nv_bfloat16 sAh[128 * WSTR];
    __shared__ __nv_bfloat16 sAl[128 * WSTR];
    __shared__ __nv_bfloat16 sWh[64 * WSTR];
    __shared__ __nv_bfloat16 sWl[64 * WSTR];

    const int tid = threadIdx.x;
    const int lane = tid & 31;
    const int wid = tid >> 5;
    const int wm = wid >> 1;
    const int wn = wid & 1;
    const int n0 = blockIdx.x * 64;
    const int m0 = blockIdx.y * 128;

    float acc[2][4][4];
#pragma unroll
    for (int mi = 0; mi < 2; mi++)
#pragma unroll
        for (int ni = 0; ni < 4; ni++)
#pragma unroll
            for (int e = 0; e < 4; e++) acc[mi][ni][e] = 0.0f;

    const int arow = (lane & 15);
    const int acol = (lane >> 4) * 8;

    for (int k0 = 0; k0 < K; k0 += 32) {
#pragma unroll
        for (int i = 0; i < 4; i++) {
            int lin = tid + i * 256;
            int row = lin >> 3, qc = lin & 7;
            float4 v = *(const float4*)(A + (size_t)(m0 + row) * K + k0 + qc * 4);
            __nv_bfloat16 hx, lx, hy, ly, hz, lz, hw, lw;
            cvt_split(v.x, hx, lx); cvt_split(v.y, hy, ly);
            cvt_split(v.z, hz, lz); cvt_split(v.w, hw, lw);
            __nv_bfloat162 p;
            p.x = hx; p.y = hy; *(__nv_bfloat162*)(sAh + row * WSTR + qc * 4) = p;
            p.x = hz; p.y = hw; *(__nv_bfloat162*)(sAh + row * WSTR + qc * 4 + 2) = p;
            p.x = lx; p.y = ly; *(__nv_bfloat162*)(sAl + row * WSTR + qc * 4) = p;
            p.x = lz; p.y = lw; *(__nv_bfloat162*)(sAl + row * WSTR + qc * 4 + 2) = p;
        }
#pragma unroll
        for (int i = 0; i < 2; i++) {
            int lin = tid + i * 256;
            int row = lin >> 3, qc = lin & 7;
            float4 v = *(const float4*)(W + (size_t)(n0 + row) * K + k0 + qc * 4);
            __nv_bfloat16 hx, lx, hy, ly, hz, lz, hw, lw;
            cvt_split(v.x, hx, lx); cvt_split(v.y, hy, ly);
            cvt_split(v.z, hz, lz); cvt_split(v.w, hw, lw);
            __nv_bfloat162 p;
            p.x = hx; p.y = hy; *(__nv_bfloat162*)(sWh + row * WSTR + qc * 4) = p;
            p.x = hz; p.y = hw; *(__nv_bfloat162*)(sWh + row * WSTR + qc * 4 + 2) = p;
            p.x = lx; p.y = ly; *(__nv_bfloat162*)(sWl + row * WSTR + qc * 4) = p;
            p.x = lz; p.y = lw; *(__nv_bfloat162*)(sWl + row * WSTR + qc * 4 + 2) = p;
        }
        __syncthreads();

#pragma unroll
        for (int ks = 0; ks < 2; ks++) {
            const int kk = ks * 16;
            uint32_t ah[2][4], al[2][4], bh[2][4], bl[2][4];
#pragma unroll
            for (int mi = 0; mi < 2; mi++) {
                int r = wm * 32 + mi * 16 + arow;
                ldm_x4(smem_u32(sAh + r * WSTR + kk + acol), ah[mi]);
                ldm_x4(smem_u32(sAl + r * WSTR + kk + acol), al[mi]);
            }
#pragma unroll
            for (int ng = 0; ng < 2; ng++) {
                int r = wn * 32 + ng * 16 + arow;
                ldm_x4(smem_u32(sWh + r * WSTR + kk + acol), bh[ng]);
                ldm_x4(smem_u32(sWl + r * WSTR + kk + acol), bl[ng]);
            }
#pragma unroll
            for (int mi = 0; mi < 2; mi++)
#pragma unroll
                for (int ng = 0; ng < 2; ng++)
#pragma unroll
                    for (int s = 0; s < 2; s++) {
                        int ni = 2 * ng + s;
                        mma16816(acc[mi][ni], ah[mi], bh[ng][s], bh[ng][s + 2]);
                        mma16816(acc[mi][ni], ah[mi], bl[ng][s], bl[ng][s + 2]);
                        mma16816(acc[mi][ni], al[mi], bh[ng][s], bh[ng][s + 2]);
                    }
        }
        __syncthreads();
    }

#pragma unroll
    for (int mi = 0; mi < 2; mi++)
#pragma unroll
        for (int ni = 0; ni < 4; ni++) {
            int m = m0 + wm * 32 + mi * 16 + (lane >> 2);
            int n = n0 + wn * 32 + ni * 8 + (lane & 3) * 2;
            float b0 = bias[n], b1 = bias[n + 1];
            float2 v0 = make_float2(acc[mi][ni][0] + b0, acc[mi][ni][1] + b1);
            float2 v1 = make_float2(acc[mi][ni][2] + b0, acc[mi][ni][3] + b1);
            *(float2*)(g_G + (size_t)m * G3_ + n) = v0;
            *(float2*)(g_G + (size_t)(m + 8) * G3_ + n) = v1;
        }
}

// ---------------- tensor-core GRU recurrence, cluster + DSMEM exchange ----------------
// grid (16 batch-groups, 4 feature-CTAs), cluster (1,4,1), 256 thr.
// Per step: gh[16x192] = h[16x256] @ Wslice[192x256]^T (split-bf16 mma.sync).
// h travels CTA->CTA via DSMEM: producers cvt_split and store hi/lo bf16 directly
// into every peer's sAh/sAl staging buffers. Barriers: split cluster arrive/wait
// (read-done) + cluster.sync (write-visible). No global atomics, no g_Hbits.
#define WROW 264                              // bf16 per row (528 B, conflict-free ldsm)
#define RW_BYTES (192 * WROW * 2)             // 101376
#define ROFF_WH 0
#define ROFF_WL RW_BYTES
#define ROFF_AH (2 * RW_BYTES)                // 202752
#define RA_BYTES (16 * WROW * 2)              // 8448
#define ROFF_AL (ROFF_AH + RA_BYTES)          // 211200
#define ROFF_GH (ROFF_AH + 2 * RA_BYTES)      // 219648 (gh: 16x192 fp32 = 12288)
#define SMEM_REC (ROFF_GH + 16 * 192 * 4)     // 231936

template <int LAYER>
__global__ __launch_bounds__(256) __cluster_dims__(1, 4, 1)
void k_recur(const float* __restrict__ whh, const float* __restrict__ bhh) {
    extern __shared__ char sm8[];
    float* Hbuf = (LAYER == 1) ? g_H1 : g_H2;

    const int tid = threadIdx.x, lane = tid & 31, wid = tid >> 5;
    const int bg = blockIdx.x;
    const int j0 = blockIdx.y * 64;
    const int bb0 = bg * 16;
    const uint32_t sb = smem_u32(sm8);
    float* gh = (float*)(sm8 + ROFF_GH);

    // ---- stage W slice once: rows n = 3*f_local + gate, fp32 -> split bf16 ----
    for (int lin = tid; lin < 192 * 64; lin += 256) {
        int n = lin >> 6, q = lin & 63;
        int f = n / 3, gate = n - 3 * f;
        float4 v = *(const float4*)(whh + (size_t)(gate * H_ + j0 + f) * H_ + 4 * q);
        __nv_bfloat16 hx, lx, hy, ly, hz, lz, hw, lw;
        cvt_split(v.x, hx, lx); cvt_split(v.y, hy, ly);
        cvt_split(v.z, hz, lz); cvt_split(v.w, hw, lw);
        __nv_bfloat162 p;
        __nv_bfloat16* wh = (__nv_bfloat16*)(sm8 + ROFF_WH) + n * WROW + 4 * q;
        __nv_bfloat16* wl = (__nv_bfloat16*)(sm8 + ROFF_WL) + n * WROW + 4 * q;
        p.x = hx; p.y = hy; *(__nv_bfloat162*)(wh) = p;
        p.x = hz; p.y = hw; *(__nv_bfloat162*)(wh + 2) = p;
        p.x = lx; p.y = ly; *(__nv_bfloat162*)(wl) = p;
        p.x = lz; p.y = lw; *(__nv_bfloat162*)(wl + 2) = p;
    }

    // per-thread roles
    const int f = tid & 63, bq = tid >> 6;     // recombine: feature f, batch quad bq
    const int j = j0 + f;
    const float br = bhh[j], bz = bhh[j + 256], bn = bhh[j + 512];

    const int nb = 24 * wid;                   // warp's first n-row
    const int arow = lane & 15, acol = (lane >> 4) * 8;
    const int xrow = nb + 16 + (lane & 7);
    const int xcol = ((lane >> 3) & 1) * 8;

    // DSMEM peer base addresses for the A staging buffers (all 4 ranks)
    uint32_t dAh[4], dAl[4];
#pragma unroll
    for (int r = 0; r < 4; r++) {
        asm("mapa.shared::cluster.u32 %0, %1, %2;" : "=r"(dAh[r]) : "r"(sb + ROFF_AH), "r"(r));
        asm("mapa.shared::cluster.u32 %0, %1, %2;" : "=r"(dAl[r]) : "r"(sb + ROFF_AL), "r"(r));
    }

    float hprev[4] = {0.f, 0.f, 0.f, 0.f};     // persistent fp32 recurrent state

    __syncthreads();

    for (int t = 0; t < T_; t++) {
        // ---- prefetch gi (DRAM), consumed in recombine ----
        float gir[4], giz[4], gin[4];
#pragma unroll
        for (int c = 0; c < 4; c++) {
            int bl = bq * 4 + c;
            size_t base = ((size_t)(bb0 + bl) * T_ + t) * G3_ + j;
            gir[c] = g_G[base];
            giz[c] = g_G[base + 256];
            gin[c] = g_G[base + 512];
        }

        if (t > 0) {
            // ---- MMA: gh = (Ah+Al)(Wh+Wl)^T, drop AlWl ----
            float acc[3][4];
#pragma unroll
            for (int ti = 0; ti < 3; ti++)
#pragma unroll
                for (int e = 0; e < 4; e++) acc[ti][e] = 0.0f;

#pragma unroll 4
            for (int kc = 0; kc < 16; kc++) {
                const int kk = kc * 16;
                uint32_t ah[4], al[4], wh4[4], wl4[4], wh2[2], wl2[2];
                ldm_x4(sb + ROFF_AH + (uint32_t)(arow * WROW + kk + acol) * 2, ah);
                ldm_x4(sb + ROFF_AL + (uint32_t)(arow * WROW + kk + acol) * 2, al);
                ldm_x4(sb + ROFF_WH + (uint32_t)((nb + arow) * WROW + kk + acol) * 2, wh4);
                ldm_x4(sb + ROFF_WL + (uint32_t)((nb + arow) * WROW + kk + acol) * 2, wl4);
                ldm_x2(sb + ROFF_WH + (uint32_t)(xrow * WROW + kk + xcol) * 2, wh2);
                ldm_x2(sb + ROFF_WL + (uint32_t)(xrow * WROW + kk + xcol) * 2, wl2);
                mma16816(acc[0], ah, wh4[0], wh4[2]);
                mma16816(acc[0], ah, wl4[0], wl4[2]);
                mma16816(acc[0], al, wh4[0], wh4[2]);
                mma16816(acc[1], ah, wh4[1], wh4[3]);
                mma16816(acc[1], ah, wl4[1], wl4[3]);
                mma16816(acc[1], al, wh4[1], wh4[3]);
                mma16816(acc[2], ah, wh2[0], wh2[1]);
                mma16816(acc[2], ah, wl2[0], wl2[1]);
                mma16816(acc[2], al, wh2[0], wh2[1]);
            }
            __syncthreads();                   // CTA-wide: all ldsm of sA done
            asm volatile("barrier.cluster.arrive.aligned;" ::: "memory");  // read-done

            // ---- c-frags -> gh smem (gh is its own buffer; safe vs peer writes) ----
#pragma unroll
            for (int ti = 0; ti < 3; ti++) {
                int col = nb + 8 * ti + 2 * (lane & 3);
                int r0 = lane >> 2;
                *(float2*)&gh[r0 * 192 + col] = make_float2(acc[ti][0], acc[ti][1]);
                *(float2*)&gh[(r0 + 8) * 192 + col] = make_float2(acc[ti][2], acc[ti][3]);
            }
            __syncthreads();
        }

        // ---- recombine: gates -> h (fp32 state in registers) ----
        float hval[4];
#pragma unroll
        for (int c = 0; c < 4; c++) {
            int bl = bq * 4 + c;
            float ghr = 0.f, ghz = 0.f, ghn = 0.f;
            if (t > 0) {
                ghr = gh[bl * 192 + 3 * f];
                ghz = gh[bl * 192 + 3 * f + 1];
                ghn = gh[bl * 192 + 3 * f + 2];
            }
            float r = fsigmoid(gir[c] + ghr + br);
            float z = fsigmoid(giz[c] + ghz + bz);
            float n = ftanh(gin[c] + r * (ghn + bn));
            float h = (1.0f - z) * n + z * hprev[c];
            hprev[c] = h;
            hval[c] = h;
            Hbuf[((size_t)(bb0 + bl) * T_ + t) * H_ + j] = h;   // fire-and-forget
        }

        // ---- wait until every CTA finished reading sA, then broadcast h(t) ----
        if (t > 0)
            asm volatile("barrier.cluster.wait.aligned;" ::: "memory");

#pragma unroll
        for (int c = 0; c < 4; c++) {
            int bl = bq * 4 + c;
            __nv_bfloat16 hh, hl;
            cvt_split(hval[c], hh, hl);
            uint16_t uh = bfbits(hh), ul = bfbits(hl);
            uint32_t off = (uint32_t)(bl * WROW + j) * 2;
#pragma unroll
            for (int r = 0; r < 4; r++) {
                asm volatile("st.shared::cluster.u16 [%0], %1;"
                             :: "r"(dAh[r] + off), "h"(uh) : "memory");
                asm volatile("st.shared::cluster.u16 [%0], %1;"
                             :: "r"(dAl[r] + off), "h"(ul) : "memory");
            }
        }
        // writes visible cluster-wide before next step's MMA
        asm volatile("barrier.cluster.arrive.aligned;" ::: "memory");
        asm volatile("barrier.cluster.wait.aligned;" ::: "memory");
    }
}

// ---------------- BN stats ----------------
__global__ __launch_bounds__(256) void k_stats() {
    int ch = threadIdx.x;
    size_t r0 = (size_t)blockIdx.x * 256;
    const float* p = g_H2 + r0 * H_ + ch;
    float s = 0.f, s2 = 0.f;
    for (int r = 0; r < 256; r++) {
        float v = p[(size_t)r * H_];
        s += v;
        s2 = fmaf(v, v, s2);
    }
    g_part[(size_t)blockIdx.x * 512 + ch] = s;
    g_part[(size_t)blockIdx.x * 512 + 256 + ch] = s2;
}

__global__ __launch_bounds__(512) void k_stats_final() {
    int i = threadIdx.x;
    float acc = 0.f;
    for (int b = 0; b < 512; b++) acc += g_part[(size_t)b * 512 + i];
    g_bnsum[i] = acc;
}

// ---------------- normalize + hardtanh + temporal mean ----------------
__global__ __launch_bounds__(256) void k_summary(const float* __restrict__ gamma,
                                                 const float* __restrict__ beta) {
    int ch = threadIdx.x;
    int b = blockIdx.x;
    const float inv_bt = 1.0f / (float)BT_;
    float mean = g_bnsum[ch] * inv_bt;
    float var = g_bnsum[256 + ch] * inv_bt - mean * mean;
    float rstd = rsqrtf(var + EPS_);
    float scale = gamma[ch] * rstd;
    float shift = beta[ch] - mean * scale;

    const float* p = g_H2 + (size_t)b * T_ * H_ + ch;
    float acc = 0.f;
    for (int t = 0; t < T_; t++) {
        float v = fmaf(p[(size_t)t * H_], scale, shift);
        v = fminf(2.0f, fmaxf(-2.0f, v));
        acc += v;
    }
    g_sum[b * H_ + ch] = acc * (1.0f / (float)T_);
}

// ---------------- final FC ----------------
__global__ __launch_bounds__(128) void k_fc(const float* __restrict__ fc_w,
                                            const float* __restrict__ fc_b,
                                            float* __restrict__ out) {
    __shared__ float s[256];
    int o = threadIdx.x;
    int b = blockIdx.x;
    s[o] = g_sum[b * H_ + o];
    s[o + 128] = g_sum[b * H_ + o + 128];
    __syncthreads();
    float acc = fc_b[o];
    const float* w = fc_w + (size_t)o * H_;
#pragma unroll 8
    for (int ch = 0; ch < H_; ch++) acc = fmaf(s[ch], w[ch], acc);
    out[b * OUT_ + o] = acc;
}

// ---------------- launch ----------------
extern "C" void kernel_launch(void* const* d_in, const int* in_sizes, int n_in,
                              void* d_out, int out_size) {
    const float* x     = (const float*)d_in[0];
    const float* w_ih1 = (const float*)d_in[1];
    const float* w_hh1 = (const float*)d_in[2];
    const float* b_ih1 = (const float*)d_in[3];
    const float* b_hh1 = (const float*)d_in[4];
    const float* w_ih2 = (const float*)d_in[5];
    const float* w_hh2 = (const float*)d_in[6];
    const float* b_ih2 = (const float*)d_in[7];
    const float* b_hh2 = (const float*)d_in[8];
    const float* gamma = (const float*)d_in[9];
    const float* beta  = (const float*)d_in[10];
    const float* fc_w  = (const float*)d_in[11];
    const float* fc_b  = (const float*)d_in[12];
    float* out = (float*)d_out;

    cudaFuncSetAttribute(k_recur<1>, cudaFuncAttributeMaxDynamicSharedMemorySize, SMEM_REC);
    cudaFuncSetAttribute(k_recur<2>, cudaFuncAttributeMaxDynamicSharedMemorySize, SMEM_REC);

    dim3 mma_grid(G3_ / 64, BT_ / 128);      // (12, 1024)
    dim3 rec_grid(16, 4);                    // 16 clusters x 4 feature CTAs

    k_mma<128, 0><<<mma_grid, 256>>>(x, w_ih1, b_ih1);
    k_recur<1><<<rec_grid, 256, SMEM_REC>>>(w_hh1, b_hh1);
    k_mma<256, 1><<<mma_grid, 256>>>(nullptr, w_ih2, b_ih2);
    k_recur<2><<<rec_grid, 256, SMEM_REC>>>(w_hh2, b_hh2);

    k_stats<<<512, 256>>>();
    k_stats_final<<<1, 512>>>();
    k_summary<<<B_, 256>>>(gamma, beta);
    k_fc<<<B_, 128>>>(fc_w, fc_b, out);
}

// round 16
// speedup vs baseline: 2.0073x; 1.1163x over previous
#include <cuda_runtime.h>
#include <cuda_bf16.h>
#include <math.h>
#include <stdint.h>
#include <string.h>

#define B_   256
#define T_   512
#define IN_  128
#define H_   256
#define G3_  768          // 3*H
#define BT_  (B_ * T_)    // 131072
#define OUT_ 128
#define EPS_ 1e-5f

// ---------------- device-global scratch ----------------
__device__ float g_G [(size_t)BT_ * G3_];   // gi for current layer (reused)
__device__ float g_H1[(size_t)BT_ * H_];    // layer-1 hidden seq (b,t,h)
__device__ float g_H2[(size_t)BT_ * H_];    // layer-2 hidden seq (b,t,h)
__device__ float g_part[512 * 512];         // BN partial sums
__device__ float g_bnsum[2 * H_];
__device__ float g_sum[B_ * H_];

// ---------------- activations / helpers ----------------
__device__ __forceinline__ float fexp2a(float x) {
    float y;
    asm("ex2.approx.f32 %0, %1;" : "=f"(y) : "f"(x));
    return y;
}
__device__ __forceinline__ float fsigmoid(float x) {
    return 1.0f / (1.0f + fexp2a(-1.4426950408889634f * x));
}
__device__ __forceinline__ float ftanh(float x) {
    float e = fexp2a(2.8853900817779268f * x);
    return 1.0f - 2.0f / (e + 1.0f);
}
__device__ __forceinline__ uint32_t smem_u32(const void* p) {
    uint32_t a;
    asm("{ .reg .u64 t; cvta.to.shared.u64 t, %1; cvt.u32.u64 %0, t; }" : "=r"(a) : "l"(p));
    return a;
}
__device__ __forceinline__ void ldm_x4(uint32_t a, uint32_t* r) {
    asm volatile("ldmatrix.sync.aligned.m8n8.x4.shared.b16 {%0,%1,%2,%3}, [%4];"
                 : "=r"(r[0]), "=r"(r[1]), "=r"(r[2]), "=r"(r[3]) : "r"(a));
}
__device__ __forceinline__ void ldm_x2(uint32_t a, uint32_t* r) {
    asm volatile("ldmatrix.sync.aligned.m8n8.x2.shared.b16 {%0,%1}, [%2];"
                 : "=r"(r[0]), "=r"(r[1]) : "r"(a));
}
__device__ __forceinline__ void mma16816(float* c, const uint32_t* a, uint32_t b0, uint32_t b1) {
    asm volatile(
        "mma.sync.aligned.m16n8k16.row.col.f32.bf16.bf16.f32 "
        "{%0,%1,%2,%3}, {%4,%5,%6,%7}, {%8,%9}, {%0,%1,%2,%3};"
        : "+f"(c[0]), "+f"(c[1]), "+f"(c[2]), "+f"(c[3])
        : "r"(a[0]), "r"(a[1]), "r"(a[2]), "r"(a[3]), "r"(b0), "r"(b1));
}
__device__ __forceinline__ void cvt_split(float v, __nv_bfloat16& h, __nv_bfloat16& l) {
    h = __float2bfloat16(v);
    l = __float2bfloat16(v - __bfloat162float(h));
}
__device__ __forceinline__ uint16_t bfbits(__nv_bfloat16 b) {
    uint16_t u; memcpy(&u, &b, 2); return u;
}

// ---------------- split-bf16 tensor-core GEMM (unchanged, verified) ----------------
#define WSTR 40   // bf16 elems per row (80 B)

template <int K, int SRC>
__global__ __launch_bounds__(256) void k_mma(const float* __restrict__ Ain,
                                             const float* __restrict__ W,
                                             const float* __restrict__ bias) {
    const float* A = (SRC == 0) ? Ain : (const float*)g_H1;   // device-side binding!

    __shared__ __nv_bfloat16 sAh[128 * WSTR];
    __shared__ __nv_bfloat16 sAl[128 * WSTR];
    __shared__ __nv_bfloat16 sWh[64 * WSTR];
    __shared__ __nv_bfloat16 sWl[64 * WSTR];

    const int tid = threadIdx.x;
    const int lane = tid & 31;
    const int wid = tid >> 5;
    const int wm = wid >> 1;
    const int wn = wid & 1;
    const int n0 = blockIdx.x * 64;
    const int m0 = blockIdx.y * 128;

    float acc[2][4][4];
#pragma unroll
    for (int mi = 0; mi < 2; mi++)
#pragma unroll
        for (int ni = 0; ni < 4; ni++)
#pragma unroll
            for (int e = 0; e < 4; e++) acc[mi][ni][e] = 0.0f;

    const int arow = (lane & 15);
    const int acol = (lane >> 4) * 8;

    for (int k0 = 0; k0 < K; k0 += 32) {
#pragma unroll
        for (int i = 0; i < 4; i++) {
            int lin = tid + i * 256;
            int row = lin >> 3, qc = lin & 7;
            float4 v = *(const float4*)(A + (size_t)(m0 + row) * K + k0 + qc * 4);
            __nv_bfloat16 hx, lx, hy, ly, hz, lz, hw, lw;
            cvt_split(v.x, hx, lx); cvt_split(v.y, hy, ly);
            cvt_split(v.z, hz, lz); cvt_split(v.w, hw, lw);
            __nv_bfloat162 p;
            p.x = hx; p.y = hy; *(__nv_bfloat162*)(sAh + row * WSTR + qc * 4) = p;
            p.x = hz; p.y = hw; *(__nv_bfloat162*)(sAh + row * WSTR + qc * 4 + 2) = p;
            p.x = lx; p.y = ly; *(__nv_bfloat162*)(sAl + row * WSTR + qc * 4) = p;
            p.x = lz; p.y = lw; *(__nv_bfloat162*)(sAl + row * WSTR + qc * 4 + 2) = p;
        }
#pragma unroll
        for (int i = 0; i < 2; i++) {
            int lin = tid + i * 256;
            int row = lin >> 3, qc = lin & 7;
            float4 v = *(const float4*)(W + (size_t)(n0 + row) * K + k0 + qc * 4);
            __nv_bfloat16 hx, lx, hy, ly, hz, lz, hw, lw;
            cvt_split(v.x, hx, lx); cvt_split(v.y, hy, ly);
            cvt_split(v.z, hz, lz); cvt_split(v.w, hw, lw);
            __nv_bfloat162 p;
            p.x = hx; p.y = hy; *(__nv_bfloat162*)(sWh + row * WSTR + qc * 4) = p;
            p.x = hz; p.y = hw; *(__nv_bfloat162*)(sWh + row * WSTR + qc * 4 + 2) = p;
            p.x = lx; p.y = ly; *(__nv_bfloat162*)(sWl + row * WSTR + qc * 4) = p;
            p.x = lz; p.y = lw; *(__nv_bfloat162*)(sWl + row * WSTR + qc * 4 + 2) = p;
        }
        __syncthreads();

#pragma unroll
        for (int ks = 0; ks < 2; ks++) {
            const int kk = ks * 16;
            uint32_t ah[2][4], al[2][4], bh[2][4], bl[2][4];
#pragma unroll
            for (int mi = 0; mi < 2; mi++) {
                int r = wm * 32 + mi * 16 + arow;
                ldm_x4(smem_u32(sAh + r * WSTR + kk + acol), ah[mi]);
                ldm_x4(smem_u32(sAl + r * WSTR + kk + acol), al[mi]);
            }
#pragma unroll
            for (int ng = 0; ng < 2; ng++) {
                int r = wn * 32 + ng * 16 + arow;
                ldm_x4(smem_u32(sWh + r * WSTR + kk + acol), bh[ng]);
                ldm_x4(smem_u32(sWl + r * WSTR + kk + acol), bl[ng]);
            }
#pragma unroll
            for (int mi = 0; mi < 2; mi++)
#pragma unroll
                for (int ng = 0; ng < 2; ng++)
#pragma unroll
                    for (int s = 0; s < 2; s++) {
                        int ni = 2 * ng + s;
                        mma16816(acc[mi][ni], ah[mi], bh[ng][s], bh[ng][s + 2]);
                        mma16816(acc[mi][ni], ah[mi], bl[ng][s], bl[ng][s + 2]);
                        mma16816(acc[mi][ni], al[mi], bh[ng][s], bh[ng][s + 2]);
                    }
        }
        __syncthreads();
    }

#pragma unroll
    for (int mi = 0; mi < 2; mi++)
#pragma unroll
        for (int ni = 0; ni < 4; ni++) {
            int m = m0 + wm * 32 + mi * 16 + (lane >> 2);
            int n = n0 + wn * 32 + ni * 8 + (lane & 3) * 2;
            float b0 = bias[n], b1 = bias[n + 1];
            float2 v0 = make_float2(acc[mi][ni][0] + b0, acc[mi][ni][1] + b1);
            float2 v1 = make_float2(acc[mi][ni][2] + b0, acc[mi][ni][3] + b1);
            *(float2*)(g_G + (size_t)m * G3_ + n) = v0;
            *(float2*)(g_G + (size_t)(m + 8) * G3_ + n) = v1;
        }
}

// ---------------- tensor-core GRU recurrence: cluster + DSMEM, double-buffered ----------------
// grid (16 batch-groups, 4 feature-CTAs), cluster (1,4,1), 256 thr.
// Per step: gh[16x192] = h[16x256] @ Wslice[192x256]^T (split-bf16 mma.sync).
// XOR-swizzled 512B rows: addr(row, colbyte) = row*512 + ((colbyte>>4 ^ (row&7))<<4) + (colbyte&15).
// Double-buffered A staging (parity t&1): ONE cluster.sync per step.
// gh aliases the just-read A[p] (dead until peers rewrite after the sync).
#define ROFF_WH 0                             // 192*512 = 98304
#define ROFF_WL 98304
#define ROFF_A  196608                        // A[p]: p*16384; hi +0 (8192), lo +8192
#define GHS 196                               // gh row stride (floats), conflict-padded
#define SMEM_REC (196608 + 2 * 16384)         // 229376

template <int LAYER>
__global__ __launch_bounds__(256) __cluster_dims__(1, 4, 1)
void k_recur(const float* __restrict__ whh, const float* __restrict__ bhh) {
    extern __shared__ char sm8[];
    float* Hbuf = (LAYER == 1) ? g_H1 : g_H2;

    const int tid = threadIdx.x, lane = tid & 31, wid = tid >> 5;
    const int bg = blockIdx.x;
    const int j0 = blockIdx.y * 64;
    const int bb0 = bg * 16;
    const uint32_t sb = smem_u32(sm8);

    // ---- stage W slice once: rows n = 3*f_local + gate, fp32 -> split bf16, swizzled ----
    for (int lin = tid; lin < 192 * 64; lin += 256) {
        int n = lin >> 6, q = lin & 63;                 // q: 4-float granule (8 B out)
        int f = n / 3, gate = n - 3 * f;
        float4 v = *(const float4*)(whh + (size_t)(gate * H_ + j0 + f) * H_ + 4 * q);
        __nv_bfloat16 hx, lx, hy, ly, hz, lz, hw, lw;
        cvt_split(v.x, hx, lx); cvt_split(v.y, hy, ly);
        cvt_split(v.z, hz, lz); cvt_split(v.w, hw, lw);
        uint32_t addr = (uint32_t)(n * 512 + (((q >> 1) ^ (n & 7)) << 4) + (q & 1) * 8);
        __nv_bfloat162 p;
        p.x = hx; p.y = hy; *(__nv_bfloat162*)(sm8 + ROFF_WH + addr) = p;
        p.x = hz; p.y = hw; *(__nv_bfloat162*)(sm8 + ROFF_WH + addr + 4) = p;
        p.x = lx; p.y = ly; *(__nv_bfloat162*)(sm8 + ROFF_WL + addr) = p;
        p.x = lz; p.y = lw; *(__nv_bfloat162*)(sm8 + ROFF_WL + addr + 4) = p;
    }

    // per-thread roles: feature pair f0=2e (local), batch pair bl0=2*bq2
    const int e = tid & 31, bq2 = tid >> 5;
    const int f0 = 2 * e;
    const int jg = j0 + f0;                             // global feature of pair start
    const float2 br2 = *(const float2*)(bhh + jg);
    const float2 bz2 = *(const float2*)(bhh + 256 + jg);
    const float2 bn2 = *(const float2*)(bhh + 512 + jg);

    const int nb = 24 * wid;
    const int arow = lane & 15, acol = (lane >> 4) * 8;
    const int xrow = nb + 16 + (lane & 7);
    const int xcol = ((lane >> 3) & 1) * 8;

    // precomputed swizzled ldsm offsets pieces
    // DSMEM peer bases for the A region
    uint32_t dA[4];
#pragma unroll
    for (int r = 0; r < 4; r++)
        asm("mapa.shared::cluster.u32 %0, %1, %2;" : "=r"(dA[r]) : "r"(sb + ROFF_A), "r"(r));

    // exchange target offsets (within A[p] buffer): for bl, column jg..jg+1
    // colbyte = jg*2 -> granule jg>>3, in-granule (f0&7)*2
    float hprev[2][2] = {{0.f, 0.f}, {0.f, 0.f}};       // [batch][feat]

    __syncthreads();

    for (int t = 0; t < T_; t++) {
        const int p = t & 1;
        const uint32_t abase = sb + ROFF_A + (uint32_t)p * 16384;
        float* gh = (float*)(sm8 + ROFF_A + p * 16384);
        const uint32_t pn_off = (uint32_t)((p ^ 1) * 16384);

        // ---- prefetch gi (DRAM) ----
        float2 gir[2], giz[2], gin[2];
#pragma unroll
        for (int cb = 0; cb < 2; cb++) {
            int bl = bq2 * 2 + cb;
            const float* gp = g_G + ((size_t)(bb0 + bl) * T_ + t) * G3_ + jg;
            gir[cb] = *(const float2*)(gp);
            giz[cb] = *(const float2*)(gp + 256);
            gin[cb] = *(const float2*)(gp + 512);
        }

        if (t > 0) {
            // ---- MMA: gh = (Ah+Al)(Wh+Wl)^T, drop AlWl ----
            float acc[3][4];
#pragma unroll
            for (int ti = 0; ti < 3; ti++)
#pragma unroll
                for (int k = 0; k < 4; k++) acc[ti][k] = 0.0f;

#pragma unroll 4
            for (int kc = 0; kc < 16; kc++) {
                const int cbyte = kc * 32 + acol * 2;           // column byte
                const int xbyte = kc * 32 + xcol * 2;
                uint32_t ah[4], al[4], wh4[4], wl4[4], wh2[2], wl2[2];
                uint32_t aoff = (uint32_t)(arow * 512 +
                                ((((cbyte >> 4) ^ (arow & 7))) << 4));
                ldm_x4(abase + aoff, ah);
                ldm_x4(abase + 8192 + aoff, al);
                int wr = nb + arow;
                uint32_t woff = (uint32_t)(wr * 512 +
                                ((((cbyte >> 4) ^ (wr & 7))) << 4));
                ldm_x4(sb + ROFF_WH + woff, wh4);
                ldm_x4(sb + ROFF_WL + woff, wl4);
                uint32_t xoff = (uint32_t)(xrow * 512 +
                                ((((xbyte >> 4) ^ (xrow & 7))) << 4));
                ldm_x2(sb + ROFF_WH + xoff, wh2);
                ldm_x2(sb + ROFF_WL + xoff, wl2);
                mma16816(acc[0], ah, wh4[0], wh4[2]);
                mma16816(acc[0], ah, wl4[0], wl4[2]);
                mma16816(acc[0], al, wh4[0], wh4[2]);
                mma16816(acc[1], ah, wh4[1], wh4[3]);
                mma16816(acc[1], ah, wl4[1], wl4[3]);
                mma16816(acc[1], al, wh4[1], wh4[3]);
                mma16816(acc[2], ah, wh2[0], wh2[1]);
                mma16816(acc[2], ah, wl2[0], wl2[1]);
                mma16816(acc[2], al, wh2[0], wh2[1]);
            }
            __syncthreads();                   // all ldsm of A[p] done (gh aliases it)

            // ---- c-frags -> gh ----
#pragma unroll
            for (int ti = 0; ti < 3; ti++) {
                int col = nb + 8 * ti + 2 * (lane & 3);
                int r0 = lane >> 2;
                *(float2*)&gh[r0 * GHS + col] = make_float2(acc[ti][0], acc[ti][1]);
                *(float2*)&gh[(r0 + 8) * GHS + col] = make_float2(acc[ti][2], acc[ti][3]);
            }
            __syncthreads();
        }

        // ---- recombine + exchange ----
#pragma unroll
        for (int cb = 0; cb < 2; cb++) {
            int bl = bq2 * 2 + cb;
            float h2[2];
#pragma unroll
            for (int cf = 0; cf < 2; cf++) {
                float ghr = 0.f, ghz = 0.f, ghn = 0.f;
                if (t > 0) {
                    const float* gp = &gh[bl * GHS + 3 * (f0 + cf)];
                    ghr = gp[0]; ghz = gp[1]; ghn = gp[2];
                }
                float gi_r = cf ? gir[cb].y : gir[cb].x;
                float gi_z = cf ? giz[cb].y : giz[cb].x;
                float gi_n = cf ? gin[cb].y : gin[cb].x;
                float b_r = cf ? br2.y : br2.x;
                float b_z = cf ? bz2.y : bz2.x;
                float b_n = cf ? bn2.y : bn2.x;
                float r = fsigmoid(gi_r + ghr + b_r);
                float z = fsigmoid(gi_z + ghz + b_z);
                float n = ftanh(gi_n + r * (ghn + b_n));
                float h = (1.0f - z) * n + z * hprev[cb][cf];
                hprev[cb][cf] = h;
                h2[cf] = h;
            }
            // global H store (float2, coalesced by e)
            *(float2*)(Hbuf + ((size_t)(bb0 + bl) * T_ + t) * H_ + jg) =
                make_float2(h2[0], h2[1]);
            // pack hi/lo pairs, DSMEM-broadcast into all ranks' A[p^1]
            __nv_bfloat16 h0h, h0l, h1h, h1l;
            cvt_split(h2[0], h0h, h0l);
            cvt_split(h2[1], h1h, h1l);
            uint32_t hi = (uint32_t)bfbits(h0h) | ((uint32_t)bfbits(h1h) << 16);
            uint32_t lo = (uint32_t)bfbits(h0l) | ((uint32_t)bfbits(h1l) << 16);
            uint32_t off = pn_off + (uint32_t)(bl * 512 +
                           (((jg >> 3) ^ (bl & 7)) << 4) + ((f0 & 7) << 1));
#pragma unroll
            for (int r = 0; r < 4; r++) {
                asm volatile("st.shared::cluster.u32 [%0], %1;"
                             :: "r"(dA[r] + off), "r"(hi) : "memory");
                asm volatile("st.shared::cluster.u32 [%0], %1;"
                             :: "r"(dA[r] + off + 8192), "r"(lo) : "memory");
            }
        }

        // ---- single cluster barrier per step ----
        asm volatile("barrier.cluster.arrive.aligned;" ::: "memory");
        asm volatile("barrier.cluster.wait.aligned;" ::: "memory");
    }
}

// ---------------- BN stats ----------------
__global__ __launch_bounds__(256) void k_stats() {
    int ch = threadIdx.x;
    size_t r0 = (size_t)blockIdx.x * 256;
    const float* p = g_H2 + r0 * H_ + ch;
    float s = 0.f, s2 = 0.f;
    for (int r = 0; r < 256; r++) {
        float v = p[(size_t)r * H_];
        s += v;
        s2 = fmaf(v, v, s2);
    }
    g_part[(size_t)blockIdx.x * 512 + ch] = s;
    g_part[(size_t)blockIdx.x * 512 + 256 + ch] = s2;
}

__global__ __launch_bounds__(512) void k_stats_final() {
    int i = threadIdx.x;
    float acc = 0.f;
    for (int b = 0; b < 512; b++) acc += g_part[(size_t)b * 512 + i];
    g_bnsum[i] = acc;
}

// ---------------- normalize + hardtanh + temporal mean ----------------
__global__ __launch_bounds__(256) void k_summary(const float* __restrict__ gamma,
                                                 const float* __restrict__ beta) {
    int ch = threadIdx.x;
    int b = blockIdx.x;
    const float inv_bt = 1.0f / (float)BT_;
    float mean = g_bnsum[ch] * inv_bt;
    float var = g_bnsum[256 + ch] * inv_bt - mean * mean;
    float rstd = rsqrtf(var + EPS_);
    float scale = gamma[ch] * rstd;
    float shift = beta[ch] - mean * scale;

    const float* p = g_H2 + (size_t)b * T_ * H_ + ch;
    float acc = 0.f;
    for (int t = 0; t < T_; t++) {
        float v = fmaf(p[(size_t)t * H_], scale, shift);
        v = fminf(2.0f, fmaxf(-2.0f, v));
        acc += v;
    }
    g_sum[b * H_ + ch] = acc * (1.0f / (float)T_);
}

// ---------------- final FC ----------------
__global__ __launch_bounds__(128) void k_fc(const float* __restrict__ fc_w,
                                            const float* __restrict__ fc_b,
                                            float* __restrict__ out) {
    __shared__ float s[256];
    int o = threadIdx.x;
    int b = blockIdx.x;
    s[o] = g_sum[b * H_ + o];
    s[o + 128] = g_sum[b * H_ + o + 128];
    __syncthreads();
    float acc = fc_b[o];
    const float* w = fc_w + (size_t)o * H_;
#pragma unroll 8
    for (int ch = 0; ch < H_; ch++) acc = fmaf(s[ch], w[ch], acc);
    out[b * OUT_ + o] = acc;
}

// ---------------- launch ----------------
extern "C" void kernel_launch(void* const* d_in, const int* in_sizes, int n_in,
                              void* d_out, int out_size) {
    const float* x     = (const float*)d_in[0];
    const float* w_ih1 = (const float*)d_in[1];
    const float* w_hh1 = (const float*)d_in[2];
    const float* b_ih1 = (const float*)d_in[3];
    const float* b_hh1 = (const float*)d_in[4];
    const float* w_ih2 = (const float*)d_in[5];
    const float* w_hh2 = (const float*)d_in[6];
    const float* b_ih2 = (const float*)d_in[7];
    const float* b_hh2 = (const float*)d_in[8];
    const float* gamma = (const float*)d_in[9];
    const float* beta  = (const float*)d_in[10];
    const float* fc_w  = (const float*)d_in[11];
    const float* fc_b  = (const float*)d_in[12];
    float* out = (float*)d_out;

    cudaFuncSetAttribute(k_recur<1>, cudaFuncAttributeMaxDynamicSharedMemorySize, SMEM_REC);
    cudaFuncSetAttribute(k_recur<2>, cudaFuncAttributeMaxDynamicSharedMemorySize, SMEM_REC);

    dim3 mma_grid(G3_ / 64, BT_ / 128);      // (12, 1024)
    dim3 rec_grid(16, 4);                    // 16 clusters x 4 feature CTAs

    k_mma<128, 0><<<mma_grid, 256>>>(x, w_ih1, b_ih1);
    k_recur<1><<<rec_grid, 256, SMEM_REC>>>(w_hh1, b_hh1);
    k_mma<256, 1><<<mma_grid, 256>>>(nullptr, w_ih2, b_ih2);
    k_recur<2><<<rec_grid, 256, SMEM_REC>>>(w_hh2, b_hh2);

    k_stats<<<512, 256>>>();
    k_stats_final<<<1, 512>>>();
    k_summary<<<B_, 256>>>(gamma, beta);
    k_fc<<<B_, 128>>>(fc_w, fc_b, out);
}